// round 6
// baseline (speedup 1.0000x reference)
#include <cuda_runtime.h>

// ---------------------------------------------------------------------------
// Triaffine:  out[n,i,j] = sum_{c,d} (h1[nic] * A[nijc]) * W3[c,d] * (h2[nid] * B[nijd])
//   A[nijc] = sum_{a,b} l1[nia] W1[abc] l2[njb]   (l1/l2 = [layer, ones])
//   B likewise with W2.
//
// v2: exact K=256 GEMMs (ones-column folded into an epilogue bias add),
// m-pair f32x2 accumulators (A pairs come free from LDS.128; B duplicated
// into (b,b) pairs with register MOVs instead of duplicated smem), BK=16.
// Crossbar traffic per 64 MACs/thread: 64B (was 96B) -> fma-pipe parity.
// ---------------------------------------------------------------------------

#define BM 128
#define BN 128
#define BK 16
#define NIT 16   // K = 256 exactly

// Scratch (module-load allocated; no runtime alloc)
__device__ __align__(16) float g_X1[2048ull * 257 * 256];
__device__ __align__(16) float g_X2[2048ull * 257 * 256];
__device__ __align__(16) float g_A [2048ull * 256 * 256];
__device__ __align__(16) float g_B [2048ull * 256 * 256];
__device__ __align__(16) float g_W3T[256 * 256];

// ---------------------------------------------------------------------------
// Inner 128x128 micro-step over BK k-slices.
// As: [BK][BM] plain.  Bs: [BK][BN] plain.
// acc[u][v] = packed pair (C[m0][n], C[m0+1][n]) with m0 = ty*8 + 2u,
// n = tx*8 + v.  A pairs are register-aliased halves of LDS.128 loads.
// ---------------------------------------------------------------------------
__device__ __forceinline__ void mm_tile16(unsigned long long acc[4][8],
                                          const float* __restrict__ As,
                                          const float* __restrict__ Bs,
                                          int ty, int tx)
{
#pragma unroll
    for (int kk = 0; kk < BK; ++kk) {
        ulonglong2 A0 = *reinterpret_cast<const ulonglong2*>(As + kk * BM + ty * 8);
        ulonglong2 A1 = *reinterpret_cast<const ulonglong2*>(As + kk * BM + ty * 8 + 4);
        unsigned long long ap[4];
        ap[0] = A0.x; ap[1] = A0.y; ap[2] = A1.x; ap[3] = A1.y;
        float4 b0 = *reinterpret_cast<const float4*>(Bs + kk * BN + tx * 8);
        float4 b1 = *reinterpret_cast<const float4*>(Bs + kk * BN + tx * 8 + 4);
        float bb[8];
        bb[0] = b0.x; bb[1] = b0.y; bb[2] = b0.z; bb[3] = b0.w;
        bb[4] = b1.x; bb[5] = b1.y; bb[6] = b1.z; bb[7] = b1.w;
#pragma unroll
        for (int v = 0; v < 8; ++v) {
            unsigned long long bp;
            asm("mov.b64 %0, {%1, %1};" : "=l"(bp) : "f"(bb[v]));
#pragma unroll
            for (int u = 0; u < 4; ++u)
                asm("fma.rn.f32x2 %0, %1, %2, %0;"
                    : "+l"(acc[u][v]) : "l"(ap[u]), "l"(bp));
        }
    }
}

__device__ __forceinline__ void unpack_acc(float c[8][8],
                                           const unsigned long long acc[4][8])
{
#pragma unroll
    for (int u = 0; u < 4; ++u)
#pragma unroll
        for (int v = 0; v < 8; ++v)
            asm("mov.b64 {%0, %1}, %2;"
                : "=f"(c[2 * u][v]), "=f"(c[2 * u + 1][v]) : "l"(acc[u][v]));
}

// ---------------------------------------------------------------------------
// K0: transpose W3 -> g_W3T
// ---------------------------------------------------------------------------
__global__ void k_transpose(const float* __restrict__ W3)
{
    __shared__ float t[32][33];
    int bx = blockIdx.x * 32, by = blockIdx.y * 32;
    t[threadIdx.y][threadIdx.x] = W3[(size_t)(by + threadIdx.y) * 256 + bx + threadIdx.x];
    __syncthreads();
    g_W3T[(size_t)(bx + threadIdx.y) * 256 + by + threadIdx.x] = t[threadIdx.x][threadIdx.y];
}

// ---------------------------------------------------------------------------
// K1: X{1,2}[m][bc] = sum_{a<256} l1[m,a] W{1,2}[a][bc] + W{1,2}[256][bc]
//     GEMM M=2048, K=256, N=65792 + bias.  grid (514, 16, 2)
// ---------------------------------------------------------------------------
__global__ void __launch_bounds__(256, 2)
k_gemm1(const float* __restrict__ layer1,
        const float* __restrict__ W1,
        const float* __restrict__ W2)
{
    const int tid = threadIdx.x;
    const int ty = tid >> 4, tx = tid & 15;
    const int nBase = blockIdx.x * BN;
    const int mBase = blockIdx.y * BM;
    const float* __restrict__ W = blockIdx.z ? W2 : W1;
    float* __restrict__ X = blockIdx.z ? g_X2 : g_X1;

    __shared__ float As[2][BK][BM];
    __shared__ float Bs[2][BK][BN];

    const int ar  = tid >> 1;           // A row within tile (0..127)
    const int kh  = (tid & 1) * 8;      // A k offset {0, 8}
    const int bkk = tid >> 4;           // B k row (0..15)
    const int bcq = (tid & 15) * 8;     // B col offset

    float va[8];
    float4 vb0, vb1;

    auto loadG = [&](int k0) {
        const float* ap = layer1 + (size_t)(mBase + ar) * 256 + k0 + kh;
        *reinterpret_cast<float4*>(va)     = *reinterpret_cast<const float4*>(ap);
        *reinterpret_cast<float4*>(va + 4) = *reinterpret_cast<const float4*>(ap + 4);
        const float* bp = W + (size_t)(k0 + bkk) * 65792 + nBase + bcq;
        vb0 = *reinterpret_cast<const float4*>(bp);
        vb1 = *reinterpret_cast<const float4*>(bp + 4);
    };
    auto stS = [&](int s) {
#pragma unroll
        for (int i = 0; i < 8; ++i) As[s][kh + i][ar] = va[i];
        *reinterpret_cast<float4*>(&Bs[s][bkk][bcq])     = vb0;
        *reinterpret_cast<float4*>(&Bs[s][bkk][bcq + 4]) = vb1;
    };

    unsigned long long acc[4][8];
#pragma unroll
    for (int u = 0; u < 4; ++u)
#pragma unroll
        for (int v = 0; v < 8; ++v) acc[u][v] = 0ull;

    loadG(0); stS(0); __syncthreads();
    for (int kt = 0; kt < NIT; ++kt) {
        if (kt + 1 < NIT) loadG((kt + 1) * BK);
        mm_tile16(acc, &As[kt & 1][0][0], &Bs[kt & 1][0][0], ty, tx);
        if (kt + 1 < NIT) { stS((kt + 1) & 1); __syncthreads(); }
    }

    float c[8][8];
    unpack_acc(c, acc);

    // bias: ones-column contribution = W[256][col]
    float bias[8];
    const float* brow = W + 256ull * 65792 + nBase + tx * 8;
    *reinterpret_cast<float4*>(bias)     = *reinterpret_cast<const float4*>(brow);
    *reinterpret_cast<float4*>(bias + 4) = *reinterpret_cast<const float4*>(brow + 4);

#pragma unroll
    for (int m = 0; m < 8; ++m) {
        float* orow = X + (size_t)(mBase + ty * 8 + m) * 65792 + nBase + tx * 8;
        float4 o0, o1;
        o0.x = c[m][0] + bias[0]; o0.y = c[m][1] + bias[1];
        o0.z = c[m][2] + bias[2]; o0.w = c[m][3] + bias[3];
        o1.x = c[m][4] + bias[4]; o1.y = c[m][5] + bias[5];
        o1.z = c[m][6] + bias[6]; o1.w = c[m][7] + bias[7];
        *reinterpret_cast<float4*>(orow)     = o0;
        *reinterpret_cast<float4*>(orow + 4) = o1;
    }
}

// ---------------------------------------------------------------------------
// K2: A[m][j,c] = sum_{b<256} l2[n,j,b] X1[m][b,c] + X1[m][256,c]
//     4096 batched GEMMs M=256, K=256, N=256 + bias.  grid (2, 2, 4096)
// ---------------------------------------------------------------------------
__global__ void __launch_bounds__(256, 2)
k_gemm2(const float* __restrict__ layer2)
{
    const int tid = threadIdx.x;
    const int ty = tid >> 4, tx = tid & 15;
    const int nt = blockIdx.x, mt = blockIdx.y;
    const int mz = blockIdx.z;
    const int m = mz >> 1, w = mz & 1;
    const int n = m >> 8;

    const float* __restrict__ X = (w ? g_X2 : g_X1) + (size_t)m * 65792;
    float* __restrict__ O       = (w ? g_B : g_A) + (size_t)m * 65536;
    const float* __restrict__ L2 = layer2 + (size_t)n * 65536;

    __shared__ float As[2][BK][BM];
    __shared__ float Bs[2][BK][BN];

    const int ar  = tid >> 1;
    const int kh  = (tid & 1) * 8;
    const int bkk = tid >> 4;
    const int bcq = (tid & 15) * 8;

    float va[8];
    float4 vb0, vb1;

    auto loadG = [&](int k0) {
        const float* ap = L2 + (size_t)(mt * BM + ar) * 256 + k0 + kh;
        *reinterpret_cast<float4*>(va)     = *reinterpret_cast<const float4*>(ap);
        *reinterpret_cast<float4*>(va + 4) = *reinterpret_cast<const float4*>(ap + 4);
        const float* bp = X + (size_t)(k0 + bkk) * 256 + nt * BN + bcq;
        vb0 = *reinterpret_cast<const float4*>(bp);
        vb1 = *reinterpret_cast<const float4*>(bp + 4);
    };
    auto stS = [&](int s) {
#pragma unroll
        for (int i = 0; i < 8; ++i) As[s][kh + i][ar] = va[i];
        *reinterpret_cast<float4*>(&Bs[s][bkk][bcq])     = vb0;
        *reinterpret_cast<float4*>(&Bs[s][bkk][bcq + 4]) = vb1;
    };

    unsigned long long acc[4][8];
#pragma unroll
    for (int u = 0; u < 4; ++u)
#pragma unroll
        for (int v = 0; v < 8; ++v) acc[u][v] = 0ull;

    loadG(0); stS(0); __syncthreads();
    for (int kt = 0; kt < NIT; ++kt) {
        if (kt + 1 < NIT) loadG((kt + 1) * BK);
        mm_tile16(acc, &As[kt & 1][0][0], &Bs[kt & 1][0][0], ty, tx);
        if (kt + 1 < NIT) { stS((kt + 1) & 1); __syncthreads(); }
    }

    float c[8][8];
    unpack_acc(c, acc);

    // bias: ones-column of l2p -> X1[m][b=256][c]
    float bias[8];
    const float* brow = X + 256ull * 256 + nt * BN + tx * 8;
    *reinterpret_cast<float4*>(bias)     = *reinterpret_cast<const float4*>(brow);
    *reinterpret_cast<float4*>(bias + 4) = *reinterpret_cast<const float4*>(brow + 4);

#pragma unroll
    for (int mm = 0; mm < 8; ++mm) {
        float* orow = O + (size_t)(mt * BM + ty * 8 + mm) * 256 + nt * BN + tx * 8;
        float4 o0, o1;
        o0.x = c[mm][0] + bias[0]; o0.y = c[mm][1] + bias[1];
        o0.z = c[mm][2] + bias[2]; o0.w = c[mm][3] + bias[3];
        o1.x = c[mm][4] + bias[4]; o1.y = c[mm][5] + bias[5];
        o1.z = c[mm][6] + bias[6]; o1.w = c[mm][7] + bias[7];
        *reinterpret_cast<float4*>(orow)     = o0;
        *reinterpret_cast<float4*>(orow + 4) = o1;
    }
}

// ---------------------------------------------------------------------------
// K3: per (m, jt):  T[j,c] = sum_d (B[m][j,d]*h2[d]) * W3T[d][c]
//     out[m][j] = sum_c (A[m][j,c]*h1[c]) * T[j,c]
//     grid (2048, 2); c processed in two 128-wide halves.
// ---------------------------------------------------------------------------
__global__ void __launch_bounds__(256, 2)
k_final(const float* __restrict__ h1,
        const float* __restrict__ h2,
        float* __restrict__ out)
{
    const int tid = threadIdx.x;
    const int ty = tid >> 4, tx = tid & 15;
    const int m = blockIdx.x, jt = blockIdx.y;

    __shared__ float As[2][BK][BM];
    __shared__ float Bs[2][BK][BN];
    __shared__ float h1s[256], h2s[256];
    __shared__ float red[16][128];

    h1s[tid] = h1[(size_t)m * 256 + tid];
    h2s[tid] = h2[(size_t)m * 256 + tid];
    __syncthreads();

    const float* __restrict__ Bm = g_B + (size_t)m * 65536 + (size_t)jt * 128 * 256;
    const float* __restrict__ Am = g_A + (size_t)m * 65536 + (size_t)jt * 128 * 256;

    float outp[8];
#pragma unroll
    for (int u = 0; u < 8; ++u) outp[u] = 0.0f;

    const int ar  = tid >> 1;
    const int kh  = (tid & 1) * 8;
    const int bkk = tid >> 4;
    const int bcq = (tid & 15) * 8;

    for (int ch = 0; ch < 2; ++ch) {
        unsigned long long acc[4][8];
#pragma unroll
        for (int u = 0; u < 4; ++u)
#pragma unroll
            for (int v = 0; v < 8; ++v) acc[u][v] = 0ull;

        float va[8];
        float4 vb0, vb1;

        auto loadG = [&](int k0) {
            int k = k0 + kh;
            const float* ap = Bm + (size_t)ar * 256 + k;
            float4 f0 = *reinterpret_cast<const float4*>(ap);
            float4 f1 = *reinterpret_cast<const float4*>(ap + 4);
            va[0] = f0.x * h2s[k];     va[1] = f0.y * h2s[k + 1];
            va[2] = f0.z * h2s[k + 2]; va[3] = f0.w * h2s[k + 3];
            va[4] = f1.x * h2s[k + 4]; va[5] = f1.y * h2s[k + 5];
            va[6] = f1.z * h2s[k + 6]; va[7] = f1.w * h2s[k + 7];
            const float* bp = g_W3T + (size_t)(k0 + bkk) * 256 + ch * 128 + bcq;
            vb0 = *reinterpret_cast<const float4*>(bp);
            vb1 = *reinterpret_cast<const float4*>(bp + 4);
        };
        auto stS = [&](int s) {
#pragma unroll
            for (int i = 0; i < 8; ++i) As[s][kh + i][ar] = va[i];
            *reinterpret_cast<float4*>(&Bs[s][bkk][bcq])     = vb0;
            *reinterpret_cast<float4*>(&Bs[s][bkk][bcq + 4]) = vb1;
        };

        loadG(0); stS(0); __syncthreads();
        for (int kt = 0; kt < NIT; ++kt) {
            if (kt + 1 < NIT) loadG((kt + 1) * BK);
            mm_tile16(acc, &As[kt & 1][0][0], &Bs[kt & 1][0][0], ty, tx);
            if (kt + 1 < NIT) { stS((kt + 1) & 1); __syncthreads(); }
        }

        float t[8][8];
        unpack_acc(t, acc);

        // epilogue: outp[j] += sum_c h1[c] * A[j,c] * T[j,c]
#pragma unroll
        for (int u = 0; u < 8; ++u) {
            const float* Arow = Am + (size_t)(ty * 8 + u) * 256 + ch * 128 + tx * 8;
            float4 a0 = *reinterpret_cast<const float4*>(Arow);
            float4 a1 = *reinterpret_cast<const float4*>(Arow + 4);
            int c0 = ch * 128 + tx * 8;
            outp[u] += a0.x * h1s[c0]     * t[u][0] + a0.y * h1s[c0 + 1] * t[u][1]
                     + a0.z * h1s[c0 + 2] * t[u][2] + a0.w * h1s[c0 + 3] * t[u][3]
                     + a1.x * h1s[c0 + 4] * t[u][4] + a1.y * h1s[c0 + 5] * t[u][5]
                     + a1.z * h1s[c0 + 6] * t[u][6] + a1.w * h1s[c0 + 7] * t[u][7];
        }
    }

    __syncthreads();
#pragma unroll
    for (int u = 0; u < 8; ++u)
        red[tx][ty * 8 + u] = outp[u];
    __syncthreads();

    if (tid < 128) {
        float s = 0.0f;
#pragma unroll
        for (int x = 0; x < 16; ++x) s += red[x][tid];
        out[(size_t)m * 256 + jt * 128 + tid] = s;
    }
}

// ---------------------------------------------------------------------------
extern "C" void kernel_launch(void* const* d_in, const int* in_sizes, int n_in,
                              void* d_out, int out_size)
{
    const float* layer1 = (const float*)d_in[0];
    const float* layer2 = (const float*)d_in[1];
    const float* h1     = (const float*)d_in[2];
    const float* h2     = (const float*)d_in[3];
    const float* W1     = (const float*)d_in[4];
    const float* W2     = (const float*)d_in[5];
    const float* W3     = (const float*)d_in[6];
    float* out = (float*)d_out;

    k_transpose<<<dim3(8, 8), dim3(32, 32)>>>(W3);
    k_gemm1<<<dim3(514, 16, 2), 256>>>(layer1, W1, W2);
    k_gemm2<<<dim3(2, 2, 4096), 256>>>(layer2);
    k_final<<<dim3(2048, 2), 256>>>(h1, h2, out);
}

// round 8
// speedup vs baseline: 1.7915x; 1.7915x over previous
#include <cuda_runtime.h>
#include <cuda_bf16.h>
#include <cstdint>

typedef uint32_t u32;

// ---------------------------------------------------------------------------
// Triaffine via 3 GEMM stages on tensor cores (mma.sync m16n8k16 bf16,
// fp32 accum). fp32 operands split x = hi + lo (bf16); D += AhBh + AhBl + AlBh.
//  K1: X{1,2}[m][bc] = sum_a l1[m,a] W{1,2}[a,bc] + W[256,bc]
//  K2: A/B[m][j,c]   = sum_b l2[n,j,b] X[m][b,c]  + X[m][256,c]
//  K3: T[j,c] = sum_d (B[m][j,d]h2[d]) W3[c,d];  out[j] = sum_c h1[c]A[j,c]T[j,c]
// CTA tile 128x128, BK=32, double-buffered padded smem, ldmatrix operands.
// B smem is K-major [k][n]; ldmatrix.x4.trans gives col-major B fragments, so
// K1/K2 stage B with no transpose. W3 is pre-transposed once into g_W3T.
// ---------------------------------------------------------------------------

__device__ __align__(16) float g_X1[2048ull * 65792];
__device__ __align__(16) float g_X2[2048ull * 65792];
__device__ __align__(16) float g_A [2048ull * 65536];
__device__ __align__(16) float g_B [2048ull * 65536];
__device__ __align__(16) float g_W3T[256 * 256];

#define A_STRIDE 80      // 128 rows(m) x 32 k bf16 (64B) + 16B pad
#define B_STRIDE 272     // 32 rows(k) x 128 n bf16 (256B) + 16B pad
#define A_TILE (128 * A_STRIDE)   // 10240 B per split per buf
#define B_TILE (32 * B_STRIDE)    // 8704  B per split per buf
#define SM_B   (4 * A_TILE)       // 40960
#define SM_H1  (SM_B + 4 * B_TILE)          // 75776
#define SM_H2  (SM_H1 + 1024)
#define SM_RED (SM_H2 + 1024)
#define SMEM_SZ (SM_RED + 1024)             // 78848

// ---------------- PTX helpers ----------------
__device__ __forceinline__ u32 smem_u32(const void* p) {
    u32 a;
    asm("{ .reg .u64 t; cvta.to.shared.u64 t, %1; cvt.u32.u64 %0, t; }" : "=r"(a) : "l"(p));
    return a;
}
__device__ __forceinline__ void ldm_x4(u32 addr, u32 r[4]) {
    asm volatile("ldmatrix.sync.aligned.m8n8.x4.shared.b16 {%0,%1,%2,%3}, [%4];"
        : "=r"(r[0]), "=r"(r[1]), "=r"(r[2]), "=r"(r[3]) : "r"(addr));
}
__device__ __forceinline__ void ldm_x4_t(u32 addr, u32 r[4]) {
    asm volatile("ldmatrix.sync.aligned.m8n8.x4.trans.shared.b16 {%0,%1,%2,%3}, [%4];"
        : "=r"(r[0]), "=r"(r[1]), "=r"(r[2]), "=r"(r[3]) : "r"(addr));
}
__device__ __forceinline__ void mma_bf16(float c[4], const u32 a[4], u32 b0, u32 b1) {
    asm volatile("mma.sync.aligned.m16n8k16.row.col.f32.bf16.bf16.f32 "
        "{%0,%1,%2,%3}, {%4,%5,%6,%7}, {%8,%9}, {%0,%1,%2,%3};"
        : "+f"(c[0]), "+f"(c[1]), "+f"(c[2]), "+f"(c[3])
        : "r"(a[0]), "r"(a[1]), "r"(a[2]), "r"(a[3]), "r"(b0), "r"(b1));
}

__device__ __forceinline__ void split8(const float* x, uint4& hi, uint4& lo) {
    u32 h[4], l[4];
#pragma unroll
    for (int i = 0; i < 4; ++i) {
        __nv_bfloat162 hh = __floats2bfloat162_rn(x[2*i], x[2*i+1]);
        float r0 = x[2*i]   - __bfloat162float(hh.x);
        float r1 = x[2*i+1] - __bfloat162float(hh.y);
        __nv_bfloat162 ll = __floats2bfloat162_rn(r0, r1);
        h[i] = *reinterpret_cast<u32*>(&hh);
        l[i] = *reinterpret_cast<u32*>(&ll);
    }
    hi = make_uint4(h[0], h[1], h[2], h[3]);
    lo = make_uint4(l[0], l[1], l[2], l[3]);
}

// ---------------------------------------------------------------------------
// Warp-tile compute over one BK=32 chunk: 2 k16-steps, 2 m-atoms, 8 n-atoms,
// 3 split-products -> 96 mma per warp. acc[mi][ni][4] fp32 fragments.
// ---------------------------------------------------------------------------
__device__ __forceinline__ void compute_chunk(float acc[2][8][4],
        u32 ah_b, u32 al_b, u32 bh_b, u32 bl_b, int warpM, int warpN, int lane)
{
    const int lr = lane & 15, lh = lane >> 4;
#pragma unroll
    for (int kk = 0; kk < 2; ++kk) {
        u32 afh[2][4], afl[2][4];
#pragma unroll
        for (int mi = 0; mi < 2; ++mi) {
            u32 ao = (u32)((warpM * 32 + mi * 16 + lr) * A_STRIDE + kk * 32 + lh * 16);
            ldm_x4(ah_b + ao, afh[mi]);
            ldm_x4(al_b + ao, afl[mi]);
        }
#pragma unroll
        for (int np = 0; np < 4; ++np) {
            u32 bo = (u32)((kk * 16 + lr) * B_STRIDE + (warpN * 64 + np * 16) * 2 + lh * 16);
            u32 bh[4], bl[4];
            ldm_x4_t(bh_b + bo, bh);
            ldm_x4_t(bl_b + bo, bl);
#pragma unroll
            for (int mi = 0; mi < 2; ++mi) {
                mma_bf16(acc[mi][np*2],   afh[mi], bh[0], bh[1]);
                mma_bf16(acc[mi][np*2],   afh[mi], bl[0], bl[1]);
                mma_bf16(acc[mi][np*2],   afl[mi], bh[0], bh[1]);
                mma_bf16(acc[mi][np*2+1], afh[mi], bh[2], bh[3]);
                mma_bf16(acc[mi][np*2+1], afh[mi], bl[2], bl[3]);
                mma_bf16(acc[mi][np*2+1], afl[mi], bh[2], bh[3]);
            }
        }
    }
}

// ---------------------------------------------------------------------------
// K0: transpose W3 -> g_W3T[d][c]
// ---------------------------------------------------------------------------
__global__ void k_transpose(const float* __restrict__ W3)
{
    __shared__ float t[32][33];
    int bx = blockIdx.x * 32, by = blockIdx.y * 32;
    t[threadIdx.y][threadIdx.x] = W3[(size_t)(by + threadIdx.y) * 256 + bx + threadIdx.x];
    __syncthreads();
    g_W3T[(size_t)(bx + threadIdx.y) * 256 + by + threadIdx.x] = t[threadIdx.x][threadIdx.y];
}

// ---------------------------------------------------------------------------
// K1: grid (514 nt, 16 mt, 2 w). D[128 m][128 bc], K=256 over a.
// ---------------------------------------------------------------------------
__global__ void __launch_bounds__(256)
k1_gemm(const float* __restrict__ layer1, const float* __restrict__ W1,
        const float* __restrict__ W2)
{
    extern __shared__ char smem[];
    const int tid = threadIdx.x, lane = tid & 31, wid = tid >> 5;
    const int warpM = wid & 3, warpN = wid >> 2;
    const size_t n0 = (size_t)blockIdx.x * 128;
    const int mBase = blockIdx.y * 128;
    const float* __restrict__ W = blockIdx.z ? W2 : W1;
    float* __restrict__ X = blockIdx.z ? g_X2 : g_X1;
    const float* Asrc = layer1 + (size_t)mBase * 256;
    const u32 sb = smem_u32(smem);

    const int arow = tid >> 1, akh = (tid & 1) * 16;
    const int bkr = tid >> 3,  bnc = (tid & 7) * 16;

    float4 va[4], vb[4];
    auto loadG = [&](int s) {
        const float* ap = Asrc + (size_t)arow * 256 + s * 32 + akh;
        va[0] = *(const float4*)ap;       va[1] = *(const float4*)(ap + 4);
        va[2] = *(const float4*)(ap + 8); va[3] = *(const float4*)(ap + 12);
        const float* bp = W + (size_t)(s * 32 + bkr) * 65792 + n0 + bnc;
        vb[0] = *(const float4*)bp;       vb[1] = *(const float4*)(bp + 4);
        vb[2] = *(const float4*)(bp + 8); vb[3] = *(const float4*)(bp + 12);
    };
    auto stS = [&](int b) {
        char* ah = smem + (b * 2 + 0) * A_TILE;
        char* al = smem + (b * 2 + 1) * A_TILE;
        char* bh = smem + SM_B + (b * 2 + 0) * B_TILE;
        char* bl = smem + SM_B + (b * 2 + 1) * B_TILE;
#pragma unroll
        for (int i = 0; i < 2; ++i) {
            uint4 hi, lo;
            split8(reinterpret_cast<const float*>(&va[i * 2]), hi, lo);
            int off = arow * A_STRIDE + (akh + i * 8) * 2;
            *(uint4*)(ah + off) = hi; *(uint4*)(al + off) = lo;
            split8(reinterpret_cast<const float*>(&vb[i * 2]), hi, lo);
            off = bkr * B_STRIDE + (bnc + i * 8) * 2;
            *(uint4*)(bh + off) = hi; *(uint4*)(bl + off) = lo;
        }
    };

    float acc[2][8][4];
#pragma unroll
    for (int mi = 0; mi < 2; ++mi)
#pragma unroll
        for (int ni = 0; ni < 8; ++ni)
#pragma unroll
            for (int q = 0; q < 4; ++q) acc[mi][ni][q] = 0.0f;

    loadG(0); stS(0); __syncthreads();
    for (int s = 0; s < 8; ++s) {
        int b = s & 1;
        if (s < 7) loadG(s + 1);
        compute_chunk(acc, sb + (b*2)*A_TILE, sb + (b*2+1)*A_TILE,
                      sb + SM_B + (b*2)*B_TILE, sb + SM_B + (b*2+1)*B_TILE,
                      warpM, warpN, lane);
        if (s < 7) { stS(b ^ 1); __syncthreads(); }
    }

    const int g = lane >> 2, t = lane & 3;
#pragma unroll
    for (int mi = 0; mi < 2; ++mi) {
        int row = mBase + warpM * 32 + mi * 16 + g;
#pragma unroll
        for (int ni = 0; ni < 8; ++ni) {
            size_t col = n0 + warpN * 64 + ni * 8 + t * 2;
            float2 bb = *(const float2*)(W + 256ull * 65792 + col);
            float* p = X + (size_t)row * 65792 + col;
            *(float2*)p = make_float2(acc[mi][ni][0] + bb.x, acc[mi][ni][1] + bb.y);
            *(float2*)(p + 8ull * 65792) =
                make_float2(acc[mi][ni][2] + bb.x, acc[mi][ni][3] + bb.y);
        }
    }
}

// ---------------------------------------------------------------------------
// K2: grid (4 = mt|nt, 2048 m, 2 w). D[128 j][128 c], K=256 over b.
// ---------------------------------------------------------------------------
__global__ void __launch_bounds__(256)
k2_gemm(const float* __restrict__ layer2)
{
    extern __shared__ char smem[];
    const int tid = threadIdx.x, lane = tid & 31, wid = tid >> 5;
    const int warpM = wid & 3, warpN = wid >> 2;
    const int mt = blockIdx.x & 1, nt = blockIdx.x >> 1;
    const int m = blockIdx.y, w = blockIdx.z;
    const float* __restrict__ Xs = (w ? g_X2 : g_X1) + (size_t)m * 65792;
    float* __restrict__ O        = (w ? g_B : g_A) + (size_t)m * 65536;
    const float* Asrc = layer2 + (size_t)(m >> 8) * 65536 + (size_t)mt * 128 * 256;
    const size_t n0 = (size_t)nt * 128;
    const u32 sb = smem_u32(smem);

    const int arow = tid >> 1, akh = (tid & 1) * 16;
    const int bkr = tid >> 3,  bnc = (tid & 7) * 16;

    float4 va[4], vb[4];
    auto loadG = [&](int s) {
        const float* ap = Asrc + (size_t)arow * 256 + s * 32 + akh;
        va[0] = *(const float4*)ap;       va[1] = *(const float4*)(ap + 4);
        va[2] = *(const float4*)(ap + 8); va[3] = *(const float4*)(ap + 12);
        const float* bp = Xs + (size_t)(s * 32 + bkr) * 256 + n0 + bnc;
        vb[0] = *(const float4*)bp;       vb[1] = *(const float4*)(bp + 4);
        vb[2] = *(const float4*)(bp + 8); vb[3] = *(const float4*)(bp + 12);
    };
    auto stS = [&](int b) {
        char* ah = smem + (b * 2 + 0) * A_TILE;
        char* al = smem + (b * 2 + 1) * A_TILE;
        char* bh = smem + SM_B + (b * 2 + 0) * B_TILE;
        char* bl = smem + SM_B + (b * 2 + 1) * B_TILE;
#pragma unroll
        for (int i = 0; i < 2; ++i) {
            uint4 hi, lo;
            split8(reinterpret_cast<const float*>(&va[i * 2]), hi, lo);
            int off = arow * A_STRIDE + (akh + i * 8) * 2;
            *(uint4*)(ah + off) = hi; *(uint4*)(al + off) = lo;
            split8(reinterpret_cast<const float*>(&vb[i * 2]), hi, lo);
            off = bkr * B_STRIDE + (bnc + i * 8) * 2;
            *(uint4*)(bh + off) = hi; *(uint4*)(bl + off) = lo;
        }
    };

    float acc[2][8][4];
#pragma unroll
    for (int mi = 0; mi < 2; ++mi)
#pragma unroll
        for (int ni = 0; ni < 8; ++ni)
#pragma unroll
            for (int q = 0; q < 4; ++q) acc[mi][ni][q] = 0.0f;

    loadG(0); stS(0); __syncthreads();
    for (int s = 0; s < 8; ++s) {
        int b = s & 1;
        if (s < 7) loadG(s + 1);
        compute_chunk(acc, sb + (b*2)*A_TILE, sb + (b*2+1)*A_TILE,
                      sb + SM_B + (b*2)*B_TILE, sb + SM_B + (b*2+1)*B_TILE,
                      warpM, warpN, lane);
        if (s < 7) { stS(b ^ 1); __syncthreads(); }
    }

    const int g = lane >> 2, t = lane & 3;
#pragma unroll
    for (int mi = 0; mi < 2; ++mi) {
        int row = mt * 128 + warpM * 32 + mi * 16 + g;
#pragma unroll
        for (int ni = 0; ni < 8; ++ni) {
            size_t col = n0 + warpN * 64 + ni * 8 + t * 2;
            float2 bb = *(const float2*)(Xs + 65536 + col);
            float* p = O + (size_t)row * 256 + col;
            *(float2*)p = make_float2(acc[mi][ni][0] + bb.x, acc[mi][ni][1] + bb.y);
            *(float2*)(p + 8ull * 256) =
                make_float2(acc[mi][ni][2] + bb.x, acc[mi][ni][3] + bb.y);
        }
    }
}

// ---------------------------------------------------------------------------
// K3: grid (2 jt, 2048 m). Two c-halves (ct) of T[128 j][128 c], K=256 over d,
// fused h1*A*T reduction into out.
// ---------------------------------------------------------------------------
__global__ void __launch_bounds__(256)
k3_final(const float* __restrict__ h1, const float* __restrict__ h2,
         float* __restrict__ out)
{
    extern __shared__ char smem[];
    const int tid = threadIdx.x, lane = tid & 31, wid = tid >> 5;
    const int warpM = wid & 3, warpN = wid >> 2;
    const int jt = blockIdx.x, m = blockIdx.y;
    float* h1s = reinterpret_cast<float*>(smem + SM_H1);
    float* h2s = reinterpret_cast<float*>(smem + SM_H2);
    float* red = reinterpret_cast<float*>(smem + SM_RED);
    const float* Asrc = g_B + (size_t)m * 65536 + (size_t)jt * 128 * 256;
    const float* Aatt = g_A + (size_t)m * 65536 + (size_t)jt * 128 * 256;
    const u32 sb = smem_u32(smem);

    h1s[tid] = h1[(size_t)m * 256 + tid];
    h2s[tid] = h2[(size_t)m * 256 + tid];

    const int arow = tid >> 1, akh = (tid & 1) * 16;
    const int bkr = tid >> 3,  bnc = (tid & 7) * 16;
    const int g = lane >> 2, t = lane & 3;

    float rs[2][2] = {{0.0f, 0.0f}, {0.0f, 0.0f}};

    for (int ct = 0; ct < 2; ++ct) {
        const size_t n0 = (size_t)ct * 128;
        float4 va[4], vb[4];
        auto loadG = [&](int s) {
            int k0 = s * 32 + akh;
            const float* ap = Asrc + (size_t)arow * 256 + k0;
            va[0] = *(const float4*)ap;       va[1] = *(const float4*)(ap + 4);
            va[2] = *(const float4*)(ap + 8); va[3] = *(const float4*)(ap + 12);
            float* vf = reinterpret_cast<float*>(va);
#pragma unroll
            for (int j = 0; j < 16; ++j) vf[j] *= h2s[k0 + j];
            const float* bp = g_W3T + (size_t)(s * 32 + bkr) * 256 + n0 + bnc;
            vb[0] = *(const float4*)bp;       vb[1] = *(const float4*)(bp + 4);
            vb[2] = *(const float4*)(bp + 8); vb[3] = *(const float4*)(bp + 12);
        };
        auto stS = [&](int b) {
            char* ah = smem + (b * 2 + 0) * A_TILE;
            char* al = smem + (b * 2 + 1) * A_TILE;
            char* bh = smem + SM_B + (b * 2 + 0) * B_TILE;
            char* bl = smem + SM_B + (b * 2 + 1) * B_TILE;
#pragma unroll
            for (int i = 0; i < 2; ++i) {
                uint4 hi, lo;
                split8(reinterpret_cast<const float*>(&va[i * 2]), hi, lo);
                int off = arow * A_STRIDE + (akh + i * 8) * 2;
                *(uint4*)(ah + off) = hi; *(uint4*)(al + off) = lo;
                split8(reinterpret_cast<const float*>(&vb[i * 2]), hi, lo);
                off = bkr * B_STRIDE + (bnc + i * 8) * 2;
                *(uint4*)(bh + off) = hi; *(uint4*)(bl + off) = lo;
            }
        };

        float acc[2][8][4];
#pragma unroll
        for (int mi = 0; mi < 2; ++mi)
#pragma unroll
            for (int ni = 0; ni < 8; ++ni)
#pragma unroll
                for (int q = 0; q < 4; ++q) acc[mi][ni][q] = 0.0f;

        __syncthreads();      // h1s/h2s ready (ct=0); prior-half reads done (ct=1)
        loadG(0); stS(0); __syncthreads();
        for (int s = 0; s < 8; ++s) {
            int b = s & 1;
            if (s < 7) loadG(s + 1);
            compute_chunk(acc, sb + (b*2)*A_TILE, sb + (b*2+1)*A_TILE,
                          sb + SM_B + (b*2)*B_TILE, sb + SM_B + (b*2+1)*B_TILE,
                          warpM, warpN, lane);
            if (s < 7) { stS(b ^ 1); __syncthreads(); }
        }

        // accumulate h1[c]*A[j,c]*T[j,c] into per-lane row partials
#pragma unroll
        for (int mi = 0; mi < 2; ++mi) {
            int j0 = warpM * 32 + mi * 16 + g;
#pragma unroll
            for (int ni = 0; ni < 8; ++ni) {
                int c = (int)n0 + warpN * 64 + ni * 8 + t * 2;
                const float* ap = Aatt + (size_t)j0 * 256 + c;
                float2 a0 = *(const float2*)ap;
                float2 a1 = *(const float2*)(ap + 8ull * 256);
                rs[mi][0] += a0.x * h1s[c] * acc[mi][ni][0]
                           + a0.y * h1s[c + 1] * acc[mi][ni][1];
                rs[mi][1] += a1.x * h1s[c] * acc[mi][ni][2]
                           + a1.y * h1s[c + 1] * acc[mi][ni][3];
            }
        }
    }

    // reduce over the 4 lanes sharing each row (t = 0..3)
#pragma unroll
    for (int mi = 0; mi < 2; ++mi)
#pragma unroll
        for (int h = 0; h < 2; ++h) {
            rs[mi][h] += __shfl_xor_sync(0xffffffffu, rs[mi][h], 1);
            rs[mi][h] += __shfl_xor_sync(0xffffffffu, rs[mi][h], 2);
        }
    __syncthreads();
    if (t == 0) {
#pragma unroll
        for (int mi = 0; mi < 2; ++mi) {
            red[warpN * 128 + warpM * 32 + mi * 16 + g]     = rs[mi][0];
            red[warpN * 128 + warpM * 32 + mi * 16 + 8 + g] = rs[mi][1];
        }
    }
    __syncthreads();
    if (tid < 128)
        out[(size_t)m * 256 + jt * 128 + tid] = red[tid] + red[128 + tid];
}

// ---------------------------------------------------------------------------
extern "C" void kernel_launch(void* const* d_in, const int* in_sizes, int n_in,
                              void* d_out, int out_size)
{
    const float* layer1 = (const float*)d_in[0];
    const float* layer2 = (const float*)d_in[1];
    const float* h1     = (const float*)d_in[2];
    const float* h2     = (const float*)d_in[3];
    const float* W1     = (const float*)d_in[4];
    const float* W2     = (const float*)d_in[5];
    const float* W3     = (const float*)d_in[6];
    float* out = (float*)d_out;

    cudaFuncSetAttribute(k1_gemm, cudaFuncAttributeMaxDynamicSharedMemorySize, SMEM_SZ);
    cudaFuncSetAttribute(k2_gemm, cudaFuncAttributeMaxDynamicSharedMemorySize, SMEM_SZ);
    cudaFuncSetAttribute(k3_final, cudaFuncAttributeMaxDynamicSharedMemorySize, SMEM_SZ);

    k_transpose<<<dim3(8, 8), dim3(32, 32)>>>(W3);
    k1_gemm<<<dim3(514, 16, 2), 256, SMEM_SZ>>>(layer1, W1, W2);
    k2_gemm<<<dim3(4, 2048, 2), 256, SMEM_SZ>>>(layer2);
    k3_final<<<dim3(2, 2048), 256, SMEM_SZ>>>(h1, h2, out);
}

// round 9
// speedup vs baseline: 2.2699x; 1.2670x over previous
#include <cuda_runtime.h>
#include <cuda_bf16.h>
#include <cstdint>

typedef uint32_t u32;

// ---------------------------------------------------------------------------
// Triaffine via 3 GEMM stages on tensor cores (mma.sync m16n8k16 bf16, fp32
// accum), split-precision: x = hi + lo (bf16), D += AhBh + AhBl + AlBh.
// v3: every GEMM operand is PRE-SPLIT into bf16 hi/lo arrays in gmem, staged
// with cp.async (no LDG->split->STS in mainloops, low regs => 2 CTAs/SM).
// h1/h2 scaling folded into K2's epilogue; K3 is pure GEMM + dot-reduce.
// ---------------------------------------------------------------------------

#define WSZ 16908544ull          // 257*65792
#define XSZ (2048ull*65792)

__device__ __nv_bfloat16 g_L1h[2048ull*256], g_L1l[2048ull*256];
__device__ __nv_bfloat16 g_L2h[2048ull*256], g_L2l[2048ull*256];
__device__ __nv_bfloat16 g_Wh[2ull*WSZ],     g_Wl[2ull*WSZ];
__device__ __nv_bfloat16 g_Xh[2ull*XSZ],     g_Xl[2ull*XSZ];
__device__ float         g_Af[2048ull*65536];                 // h1-scaled A_l (fp32)
__device__ __nv_bfloat16 g_Bh[2048ull*65536], g_Bl[2048ull*65536]; // h2-scaled A_r (split)
__device__ __nv_bfloat16 g_W3Th[256*256], g_W3Tl[256*256];

#define A_STRIDE 80
#define B_STRIDE 272
#define A_TILE (128 * A_STRIDE)   // 10240
#define B_TILE (32 * B_STRIDE)    // 8704
#define SM_B   (4 * A_TILE)       // 40960
#define SM_H   (SM_B + 4 * B_TILE)        // 75776
#define SM_RED (SM_H + 512)               // 76288
#define SMEM_SZ (SM_RED + 1024)           // 77312

// ---------------- PTX helpers ----------------
__device__ __forceinline__ u32 smem_u32(const void* p) {
    u32 a;
    asm("{ .reg .u64 t; cvta.to.shared.u64 t, %1; cvt.u32.u64 %0, t; }" : "=r"(a) : "l"(p));
    return a;
}
__device__ __forceinline__ void cpa16(u32 s, const void* g) {
    asm volatile("cp.async.cg.shared.global [%0], [%1], 16;" :: "r"(s), "l"(g));
}
#define CPA_COMMIT() asm volatile("cp.async.commit_group;" ::: "memory")
#define CPA_WAIT(n)  asm volatile("cp.async.wait_group %0;" :: "n"(n) : "memory")

__device__ __forceinline__ void ldm_x4(u32 addr, u32 r[4]) {
    asm volatile("ldmatrix.sync.aligned.m8n8.x4.shared.b16 {%0,%1,%2,%3}, [%4];"
        : "=r"(r[0]), "=r"(r[1]), "=r"(r[2]), "=r"(r[3]) : "r"(addr));
}
__device__ __forceinline__ void ldm_x4_t(u32 addr, u32 r[4]) {
    asm volatile("ldmatrix.sync.aligned.m8n8.x4.trans.shared.b16 {%0,%1,%2,%3}, [%4];"
        : "=r"(r[0]), "=r"(r[1]), "=r"(r[2]), "=r"(r[3]) : "r"(addr));
}
__device__ __forceinline__ void mma_bf16(float c[4], const u32 a[4], u32 b0, u32 b1) {
    asm volatile("mma.sync.aligned.m16n8k16.row.col.f32.bf16.bf16.f32 "
        "{%0,%1,%2,%3}, {%4,%5,%6,%7}, {%8,%9}, {%0,%1,%2,%3};"
        : "+f"(c[0]), "+f"(c[1]), "+f"(c[2]), "+f"(c[3])
        : "r"(a[0]), "r"(a[1]), "r"(a[2]), "r"(a[3]), "r"(b0), "r"(b1));
}
__device__ __forceinline__ void split2(float a, float b, u32& hi, u32& lo) {
    __nv_bfloat162 hh = __floats2bfloat162_rn(a, b);
    float r0 = a - __bfloat162float(hh.x);
    float r1 = b - __bfloat162float(hh.y);
    __nv_bfloat162 ll = __floats2bfloat162_rn(r0, r1);
    hi = *reinterpret_cast<u32*>(&hh);
    lo = *reinterpret_cast<u32*>(&ll);
}

// ---------------------------------------------------------------------------
// cp.async staging of one BK=32 chunk (A: 128x32, B: 32x128, hi+lo splits).
// bh/bl pre-offset by column base; pitches in elements.
// ---------------------------------------------------------------------------
__device__ __forceinline__ void stage_tiles(u32 sb, int buf, int tid,
    const __nv_bfloat16* __restrict__ ah, const __nv_bfloat16* __restrict__ al,
    size_t apitch,
    const __nv_bfloat16* __restrict__ bh, const __nv_bfloat16* __restrict__ bl,
    size_t bpitch, int k0)
{
    const int arow = tid >> 1, ac = tid & 1;
    const int brow = tid >> 3, bc = tid & 7;
    const __nv_bfloat16* g = ah + (size_t)arow * apitch + k0 + ac * 16;
    u32 s = sb + (buf * 2) * A_TILE + arow * A_STRIDE + ac * 32;
    cpa16(s, g); cpa16(s + 16, g + 8);
    g = al + (size_t)arow * apitch + k0 + ac * 16;
    s = sb + (buf * 2 + 1) * A_TILE + arow * A_STRIDE + ac * 32;
    cpa16(s, g); cpa16(s + 16, g + 8);
    g = bh + (size_t)(k0 + brow) * bpitch + bc * 16;
    s = sb + SM_B + (buf * 2) * B_TILE + brow * B_STRIDE + bc * 32;
    cpa16(s, g); cpa16(s + 16, g + 8);
    g = bl + (size_t)(k0 + brow) * bpitch + bc * 16;
    s = sb + SM_B + (buf * 2 + 1) * B_TILE + brow * B_STRIDE + bc * 32;
    cpa16(s, g); cpa16(s + 16, g + 8);
}

// ---------------------------------------------------------------------------
// Warp-tile compute over one BK=32 chunk (as R8): 96 mma per warp.
// ---------------------------------------------------------------------------
__device__ __forceinline__ void compute_chunk(float acc[2][8][4],
        u32 ah_b, u32 al_b, u32 bh_b, u32 bl_b, int warpM, int warpN, int lane)
{
    const int lr = lane & 15, lh = lane >> 4;
#pragma unroll
    for (int kk = 0; kk < 2; ++kk) {
        u32 afh[2][4], afl[2][4];
#pragma unroll
        for (int mi = 0; mi < 2; ++mi) {
            u32 ao = (u32)((warpM * 32 + mi * 16 + lr) * A_STRIDE + kk * 32 + lh * 16);
            ldm_x4(ah_b + ao, afh[mi]);
            ldm_x4(al_b + ao, afl[mi]);
        }
#pragma unroll
        for (int np = 0; np < 4; ++np) {
            u32 bo = (u32)((kk * 16 + lr) * B_STRIDE + (warpN * 64 + np * 16) * 2 + lh * 16);
            u32 bh[4], bl[4];
            ldm_x4_t(bh_b + bo, bh);
            ldm_x4_t(bl_b + bo, bl);
#pragma unroll
            for (int mi = 0; mi < 2; ++mi) {
                mma_bf16(acc[mi][np*2],   afh[mi], bh[0], bh[1]);
                mma_bf16(acc[mi][np*2],   afh[mi], bl[0], bl[1]);
                mma_bf16(acc[mi][np*2],   afl[mi], bh[0], bh[1]);
                mma_bf16(acc[mi][np*2+1], afh[mi], bh[2], bh[3]);
                mma_bf16(acc[mi][np*2+1], afh[mi], bl[2], bl[3]);
                mma_bf16(acc[mi][np*2+1], afl[mi], bh[2], bh[3]);
            }
        }
    }
}

#define MAINLOOP(STAGE_CALL)                                                  \
    STAGE_CALL(0, 0); CPA_COMMIT();                                           \
    STAGE_CALL(1, 1); CPA_COMMIT();                                           \
    for (int s = 0; s < 8; ++s) {                                             \
        int b = s & 1;                                                        \
        if (s == 7) { CPA_WAIT(0); } else { CPA_WAIT(1); }                    \
        __syncthreads();                                                      \
        compute_chunk(acc, sb + (b*2)*A_TILE, sb + (b*2+1)*A_TILE,            \
                      sb + SM_B + (b*2)*B_TILE, sb + SM_B + (b*2+1)*B_TILE,   \
                      warpM, warpN, lane);                                    \
        __syncthreads();                                                      \
        if (s < 6) { STAGE_CALL(b, s + 2); CPA_COMMIT(); }                    \
    }

// ---------------------------------------------------------------------------
// Prep: elementwise fp32 -> (hi, lo) bf16
// ---------------------------------------------------------------------------
__global__ void k_split_lin(const float* __restrict__ src, int dest, size_t cnt)
{
    size_t i = ((size_t)blockIdx.x * 256 + threadIdx.x) * 4;
    if (i >= cnt) return;
    __nv_bfloat16 *dh, *dl;
    switch (dest) {
        case 0:  dh = g_L1h;      dl = g_L1l;      break;
        case 1:  dh = g_L2h;      dl = g_L2l;      break;
        case 2:  dh = g_Wh;       dl = g_Wl;       break;
        default: dh = g_Wh + WSZ; dl = g_Wl + WSZ; break;
    }
    float4 v = *reinterpret_cast<const float4*>(src + i);
    u32 h0, l0, h1, l1;
    split2(v.x, v.y, h0, l0);
    split2(v.z, v.w, h1, l1);
    *reinterpret_cast<uint2*>(dh + i) = make_uint2(h0, h1);
    *reinterpret_cast<uint2*>(dl + i) = make_uint2(l0, l1);
}

// transpose + split W3 -> W3T[d][c] = W3[c][d]
__global__ void k_prep_w3(const float* __restrict__ W3)
{
    __shared__ float t[32][33];
    int bx = blockIdx.x * 32, by = blockIdx.y * 32;
    t[threadIdx.y][threadIdx.x] = W3[(size_t)(by + threadIdx.y) * 256 + bx + threadIdx.x];
    __syncthreads();
    float v = t[threadIdx.x][threadIdx.y];
    __nv_bfloat16 h = __float2bfloat16(v);
    size_t o = (size_t)(bx + threadIdx.y) * 256 + by + threadIdx.x;
    g_W3Th[o] = h;
    g_W3Tl[o] = __float2bfloat16(v - __bfloat162float(h));
}

// ---------------------------------------------------------------------------
// K1: grid (16 mt, 514 nt, 2 w). D[128 m][128 bc], K=256 over a.
// Output: X split into g_Xh/g_Xl (+ bias row W[256]).
// ---------------------------------------------------------------------------
__global__ void __launch_bounds__(256, 2)
k1_gemm()
{
    extern __shared__ char smem[];
    const int tid = threadIdx.x, lane = tid & 31, wid = tid >> 5;
    const int warpM = wid & 3, warpN = wid >> 2;
    const int mBase = blockIdx.x * 128;
    const size_t n0 = (size_t)blockIdx.y * 128;
    const int w = blockIdx.z;
    const __nv_bfloat16* WhP = g_Wh + (size_t)w * WSZ + n0;
    const __nv_bfloat16* WlP = g_Wl + (size_t)w * WSZ + n0;
    __nv_bfloat16* Xh = g_Xh + (size_t)w * XSZ;
    __nv_bfloat16* Xl = g_Xl + (size_t)w * XSZ;
    const __nv_bfloat16* AhP = g_L1h + (size_t)mBase * 256;
    const __nv_bfloat16* AlP = g_L1l + (size_t)mBase * 256;
    const u32 sb = smem_u32(smem);

    float acc[2][8][4];
#pragma unroll
    for (int mi = 0; mi < 2; ++mi)
#pragma unroll
        for (int ni = 0; ni < 8; ++ni)
#pragma unroll
            for (int q = 0; q < 4; ++q) acc[mi][ni][q] = 0.0f;

#define K1_STAGE(buf, s) stage_tiles(sb, buf, tid, AhP, AlP, 256, WhP, WlP, 65792, (s) * 32)
    MAINLOOP(K1_STAGE)
#undef K1_STAGE

    const int g = lane >> 2, t = lane & 3;
#pragma unroll
    for (int mi = 0; mi < 2; ++mi) {
        int row = mBase + warpM * 32 + mi * 16 + g;
#pragma unroll
        for (int ni = 0; ni < 8; ++ni) {
            size_t colL = warpN * 64 + ni * 8 + t * 2;
            u32 wh2 = *reinterpret_cast<const u32*>(WhP + 256ull * 65792 + colL);
            u32 wl2 = *reinterpret_cast<const u32*>(WlP + 256ull * 65792 + colL);
            __nv_bfloat162 hh = *reinterpret_cast<__nv_bfloat162*>(&wh2);
            __nv_bfloat162 ll = *reinterpret_cast<__nv_bfloat162*>(&wl2);
            float b0 = __bfloat162float(hh.x) + __bfloat162float(ll.x);
            float b1 = __bfloat162float(hh.y) + __bfloat162float(ll.y);
            size_t col = n0 + colL;
            u32 hi, lo;
            split2(acc[mi][ni][0] + b0, acc[mi][ni][1] + b1, hi, lo);
            *reinterpret_cast<u32*>(Xh + (size_t)row * 65792 + col) = hi;
            *reinterpret_cast<u32*>(Xl + (size_t)row * 65792 + col) = lo;
            split2(acc[mi][ni][2] + b0, acc[mi][ni][3] + b1, hi, lo);
            *reinterpret_cast<u32*>(Xh + (size_t)(row + 8) * 65792 + col) = hi;
            *reinterpret_cast<u32*>(Xl + (size_t)(row + 8) * 65792 + col) = lo;
        }
    }
}

// ---------------------------------------------------------------------------
// K2: grid (4 = mt + 2*nt, 2048 m, 2 w). D[128 j][128 c], K=256 over b.
// w=0: g_Af = (res + bias)*h1 (fp32);  w=1: g_Bh/g_Bl = split((res + bias)*h2).
// ---------------------------------------------------------------------------
__global__ void __launch_bounds__(256, 2)
k2_gemm(const float* __restrict__ h1, const float* __restrict__ h2)
{
    extern __shared__ char smem[];
    const int tid = threadIdx.x, lane = tid & 31, wid = tid >> 5;
    const int warpM = wid & 3, warpN = wid >> 2;
    const int mt = blockIdx.x & 1, nt = blockIdx.x >> 1;
    const int m = blockIdx.y, w = blockIdx.z;
    const size_t n0 = (size_t)nt * 128;
    const __nv_bfloat16* XhP = g_Xh + (size_t)w * XSZ + (size_t)m * 65792 + n0;
    const __nv_bfloat16* XlP = g_Xl + (size_t)w * XSZ + (size_t)m * 65792 + n0;
    const __nv_bfloat16* AhP = g_L2h + ((size_t)(m >> 8) * 256 + mt * 128) * 256;
    const __nv_bfloat16* AlP = g_L2l + ((size_t)(m >> 8) * 256 + mt * 128) * 256;
    const u32 sb = smem_u32(smem);
    float* hsm = reinterpret_cast<float*>(smem + SM_H);

    if (tid < 128)
        hsm[tid] = (w ? h2 : h1)[(size_t)m * 256 + n0 + tid];

    float acc[2][8][4];
#pragma unroll
    for (int mi = 0; mi < 2; ++mi)
#pragma unroll
        for (int ni = 0; ni < 8; ++ni)
#pragma unroll
            for (int q = 0; q < 4; ++q) acc[mi][ni][q] = 0.0f;

#define K2_STAGE(buf, s) stage_tiles(sb, buf, tid, AhP, AlP, 256, XhP, XlP, 256, (s) * 32)
    MAINLOOP(K2_STAGE)
#undef K2_STAGE

    const int g = lane >> 2, t = lane & 3;
#pragma unroll
    for (int mi = 0; mi < 2; ++mi) {
        int row = mt * 128 + warpM * 32 + mi * 16 + g;
#pragma unroll
        for (int ni = 0; ni < 8; ++ni) {
            int colL = warpN * 64 + ni * 8 + t * 2;
            // bias = X[m][b=256][c]  (offset within the pre-column-offset XhP)
            u32 xh2 = *reinterpret_cast<const u32*>(XhP + 256ull * 256 + colL);
            u32 xl2 = *reinterpret_cast<const u32*>(XlP + 256ull * 256 + colL);
            __nv_bfloat162 hh = *reinterpret_cast<__nv_bfloat162*>(&xh2);
            __nv_bfloat162 ll = *reinterpret_cast<__nv_bfloat162*>(&xl2);
            float b0 = __bfloat162float(hh.x) + __bfloat162float(ll.x);
            float b1 = __bfloat162float(hh.y) + __bfloat162float(ll.y);
            float s0 = hsm[colL], s1 = hsm[colL + 1];
            size_t col = n0 + colL;
            float v00 = (acc[mi][ni][0] + b0) * s0, v01 = (acc[mi][ni][1] + b1) * s1;
            float v10 = (acc[mi][ni][2] + b0) * s0, v11 = (acc[mi][ni][3] + b1) * s1;
            if (w == 0) {
                float* p = g_Af + (size_t)m * 65536 + (size_t)row * 256 + col;
                *reinterpret_cast<float2*>(p) = make_float2(v00, v01);
                *reinterpret_cast<float2*>(p + 8ull * 256) = make_float2(v10, v11);
            } else {
                size_t o = (size_t)m * 65536 + (size_t)row * 256 + col;
                u32 hi, lo;
                split2(v00, v01, hi, lo);
                *reinterpret_cast<u32*>(g_Bh + o) = hi;
                *reinterpret_cast<u32*>(g_Bl + o) = lo;
                split2(v10, v11, hi, lo);
                *reinterpret_cast<u32*>(g_Bh + o + 8ull * 256) = hi;
                *reinterpret_cast<u32*>(g_Bl + o + 8ull * 256) = lo;
            }
        }
    }
}

// ---------------------------------------------------------------------------
// K3: grid (2 jt, 2048 m). Two c-halves of T[128 j][128 c], K=256 over d,
// fused Af*T reduction -> out.
// ---------------------------------------------------------------------------
__global__ void __launch_bounds__(256, 2)
k3_final(float* __restrict__ out)
{
    extern __shared__ char smem[];
    const int tid = threadIdx.x, lane = tid & 31, wid = tid >> 5;
    const int warpM = wid & 3, warpN = wid >> 2;
    const int jt = blockIdx.x, m = blockIdx.y;
    const __nv_bfloat16* AhP = g_Bh + (size_t)m * 65536 + (size_t)jt * 128 * 256;
    const __nv_bfloat16* AlP = g_Bl + (size_t)m * 65536 + (size_t)jt * 128 * 256;
    const float* AfP = g_Af + (size_t)m * 65536 + (size_t)jt * 128 * 256;
    const u32 sb = smem_u32(smem);
    float* red = reinterpret_cast<float*>(smem + SM_RED);
    const int g = lane >> 2, t = lane & 3;

    float rs[2][2] = {{0.0f, 0.0f}, {0.0f, 0.0f}};

    for (int ct = 0; ct < 2; ++ct) {
        const __nv_bfloat16* BhP = g_W3Th + ct * 128;
        const __nv_bfloat16* BlP = g_W3Tl + ct * 128;

        float acc[2][8][4];
#pragma unroll
        for (int mi = 0; mi < 2; ++mi)
#pragma unroll
            for (int ni = 0; ni < 8; ++ni)
#pragma unroll
                for (int q = 0; q < 4; ++q) acc[mi][ni][q] = 0.0f;

#define K3_STAGE(buf, s) stage_tiles(sb, buf, tid, AhP, AlP, 256, BhP, BlP, 256, (s) * 32)
        MAINLOOP(K3_STAGE)
#undef K3_STAGE

#pragma unroll
        for (int mi = 0; mi < 2; ++mi) {
            int j0 = warpM * 32 + mi * 16 + g;
#pragma unroll
            for (int ni = 0; ni < 8; ++ni) {
                int c = ct * 128 + warpN * 64 + ni * 8 + t * 2;
                const float* ap = AfP + (size_t)j0 * 256 + c;
                float2 a0 = *reinterpret_cast<const float2*>(ap);
                float2 a1 = *reinterpret_cast<const float2*>(ap + 8ull * 256);
                rs[mi][0] += a0.x * acc[mi][ni][0] + a0.y * acc[mi][ni][1];
                rs[mi][1] += a1.x * acc[mi][ni][2] + a1.y * acc[mi][ni][3];
            }
        }
    }

#pragma unroll
    for (int mi = 0; mi < 2; ++mi)
#pragma unroll
        for (int h = 0; h < 2; ++h) {
            rs[mi][h] += __shfl_xor_sync(0xffffffffu, rs[mi][h], 1);
            rs[mi][h] += __shfl_xor_sync(0xffffffffu, rs[mi][h], 2);
        }
    __syncthreads();
    if (t == 0) {
#pragma unroll
        for (int mi = 0; mi < 2; ++mi) {
            red[warpN * 128 + warpM * 32 + mi * 16 + g]     = rs[mi][0];
            red[warpN * 128 + warpM * 32 + mi * 16 + 8 + g] = rs[mi][1];
        }
    }
    __syncthreads();
    if (tid < 128)
        out[(size_t)m * 256 + jt * 128 + tid] = red[tid] + red[128 + tid];
}

// ---------------------------------------------------------------------------
extern "C" void kernel_launch(void* const* d_in, const int* in_sizes, int n_in,
                              void* d_out, int out_size)
{
    const float* layer1 = (const float*)d_in[0];
    const float* layer2 = (const float*)d_in[1];
    const float* h1     = (const float*)d_in[2];
    const float* h2     = (const float*)d_in[3];
    const float* W1     = (const float*)d_in[4];
    const float* W2     = (const float*)d_in[5];
    const float* W3     = (const float*)d_in[6];
    float* out = (float*)d_out;

    cudaFuncSetAttribute(k1_gemm,  cudaFuncAttributeMaxDynamicSharedMemorySize, SMEM_SZ);
    cudaFuncSetAttribute(k2_gemm,  cudaFuncAttributeMaxDynamicSharedMemorySize, SMEM_SZ);
    cudaFuncSetAttribute(k3_final, cudaFuncAttributeMaxDynamicSharedMemorySize, SMEM_SZ);

    k_split_lin<<<512,   256>>>(layer1, 0, 524288ull);
    k_split_lin<<<512,   256>>>(layer2, 1, 524288ull);
    k_split_lin<<<16513, 256>>>(W1, 2, WSZ);
    k_split_lin<<<16513, 256>>>(W2, 3, WSZ);
    k_prep_w3<<<dim3(8, 8), dim3(32, 32)>>>(W3);

    k1_gemm<<<dim3(16, 514, 2), 256, SMEM_SZ>>>();
    k2_gemm<<<dim3(4, 2048, 2), 256, SMEM_SZ>>>(h1, h2);
    k3_final<<<dim3(2, 2048),   256, SMEM_SZ>>>(out);
}

// round 10
// speedup vs baseline: 3.9331x; 1.7327x over previous
#include <cuda_runtime.h>
#include <cuda_fp16.h>
#include <cstdint>

typedef uint32_t u32;

// ---------------------------------------------------------------------------
// Triaffine via 3 GEMM stages on tensor cores (mma.sync m16n8k16 fp16, fp32
// accum). Split scheme: M-side operand = exact fp16 hi/lo pair, B-side =
// single fp16  =>  D = Ah*B + Al*B   (2 mma per k-step instead of 3).
//  K1: X{1,2}[m][bc] = l1(pair) @ W{1,2}(fp16)  + bias W[256]   -> X fp16
//  K2: A_l = L2(pair) @ X1(fp16) + bias, *h1 -> fp32 scratch
//      A_r = L2(pair) @ X2(fp16) + bias, *h2 -> fp16 pair scratch
//  K3: T = A_r(pair) @ W3T(fp16);  out[j] = sum_c A_l[j,c] * T[j,c]
// Pipeline: cp.async, 3 smem buffers, XOR-swizzled (no padding), one
// __syncthreads per BK=32 stage, 2 CTAs/SM.
// ---------------------------------------------------------------------------

#define WSZ 16908544ull              // 257*65792
#define XSZ (2048ull*65792)

__device__ __half g_L1h[2048ull*256], g_L1l[2048ull*256];
__device__ __half g_L2h[2048ull*256], g_L2l[2048ull*256];
__device__ __half g_W[2ull*WSZ];                   // W1 | W2 (single fp16)
__device__ __half g_X[2ull*XSZ];                   // X1 | X2 (single fp16)
__device__ float  g_Af[2048ull*65536];             // h1-scaled A_l (fp32)
__device__ __half g_Ah[2048ull*65536], g_Al[2048ull*65536];  // h2-scaled A_r pair
__device__ __half g_W3T[256*256];                  // W3T[d][c] (single fp16)

// smem: per buffer [Ah 8192 | Al 8192 | B 8192] x 3 buffers
#define BUF_SZ  24576
#define SM_H    73728
#define SM_RED  (SM_H + 512)
#define SMEM_SZ (SM_RED + 1024)      // 75264 -> 2 CTAs/SM

// ---------------- PTX helpers ----------------
__device__ __forceinline__ u32 smem_u32(const void* p) {
    u32 a;
    asm("{ .reg .u64 t; cvta.to.shared.u64 t, %1; cvt.u32.u64 %0, t; }" : "=r"(a) : "l"(p));
    return a;
}
__device__ __forceinline__ void cpa16(u32 s, const void* g) {
    asm volatile("cp.async.cg.shared.global [%0], [%1], 16;" :: "r"(s), "l"(g));
}
#define CPA_COMMIT() asm volatile("cp.async.commit_group;" ::: "memory")
#define CPA_WAIT(n)  asm volatile("cp.async.wait_group %0;" :: "n"(n) : "memory")

__device__ __forceinline__ void ldm_x4(u32 addr, u32 r[4]) {
    asm volatile("ldmatrix.sync.aligned.m8n8.x4.shared.b16 {%0,%1,%2,%3}, [%4];"
        : "=r"(r[0]), "=r"(r[1]), "=r"(r[2]), "=r"(r[3]) : "r"(addr));
}
__device__ __forceinline__ void ldm_x4_t(u32 addr, u32 r[4]) {
    asm volatile("ldmatrix.sync.aligned.m8n8.x4.trans.shared.b16 {%0,%1,%2,%3}, [%4];"
        : "=r"(r[0]), "=r"(r[1]), "=r"(r[2]), "=r"(r[3]) : "r"(addr));
}
__device__ __forceinline__ void mma_f16(float c[4], const u32 a[4], u32 b0, u32 b1) {
    asm volatile("mma.sync.aligned.m16n8k16.row.col.f32.f16.f16.f32 "
        "{%0,%1,%2,%3}, {%4,%5,%6,%7}, {%8,%9}, {%0,%1,%2,%3};"
        : "+f"(c[0]), "+f"(c[1]), "+f"(c[2]), "+f"(c[3])
        : "r"(a[0]), "r"(a[1]), "r"(a[2]), "r"(a[3]), "r"(b0), "r"(b1));
}

// XOR-swizzled addresses (chunk = 16B unit within a row)
__device__ __forceinline__ u32 sw_a(u32 base, int row, int c) {      // A: 64B rows
    return base + row * 64 + ((c ^ ((row >> 1) & 3)) << 4);
}
__device__ __forceinline__ u32 sw_b(u32 base, int row, int c) {      // B: 256B rows
    return base + row * 256 + ((c ^ (row & 7)) << 4);
}

// ---------------------------------------------------------------------------
// Stage one BK=32 chunk: A pair 128x32 fp16 (hi+lo), B single 32x128 fp16.
// ---------------------------------------------------------------------------
__device__ __forceinline__ void stage_tiles(u32 sb, int buf, int tid,
    const __half* __restrict__ ah, const __half* __restrict__ al, size_t apitch,
    const __half* __restrict__ b, size_t bpitch, int k0)
{
    const int arow = tid >> 1, ac = tid & 1;
    const int brow = tid >> 3, bc = tid & 7;
    const u32 base = sb + buf * BUF_SZ;
    const __half* g = ah + (size_t)arow * apitch + k0 + ac * 16;
    cpa16(sw_a(base, arow, ac * 2), g);
    cpa16(sw_a(base, arow, ac * 2 + 1), g + 8);
    g = al + (size_t)arow * apitch + k0 + ac * 16;
    cpa16(sw_a(base + 8192, arow, ac * 2), g);
    cpa16(sw_a(base + 8192, arow, ac * 2 + 1), g + 8);
    g = b + (size_t)(k0 + brow) * bpitch + bc * 16;
    cpa16(sw_b(base + 16384, brow, bc * 2), g);
    cpa16(sw_b(base + 16384, brow, bc * 2 + 1), g + 8);
}

// ---------------------------------------------------------------------------
// Warp tile 32x128 over one BK=32 chunk: 64 mma per warp (2-term split).
// ---------------------------------------------------------------------------
__device__ __forceinline__ void compute_chunk(float acc[2][8][4],
        u32 base, int warpM, int warpN, int lane)
{
    const int lr = lane & 15, lh = lane >> 4;
    const u32 aB = base, alB = base + 8192, bB = base + 16384;
#pragma unroll
    for (int kk = 0; kk < 2; ++kk) {
        u32 afh[2][4], afl[2][4];
#pragma unroll
        for (int mi = 0; mi < 2; ++mi) {
            int row = warpM * 32 + mi * 16 + lr;
            int c = kk * 2 + lh;
            ldm_x4(sw_a(aB, row, c), afh[mi]);
            ldm_x4(sw_a(alB, row, c), afl[mi]);
        }
#pragma unroll
        for (int np = 0; np < 4; ++np) {
            int row = kk * 16 + lr;
            int c = warpN * 8 + np * 2 + lh;
            u32 bf[4];
            ldm_x4_t(sw_b(bB, row, c), bf);
#pragma unroll
            for (int mi = 0; mi < 2; ++mi) {
                mma_f16(acc[mi][np*2],   afh[mi], bf[0], bf[1]);
                mma_f16(acc[mi][np*2],   afl[mi], bf[0], bf[1]);
                mma_f16(acc[mi][np*2+1], afh[mi], bf[2], bf[3]);
                mma_f16(acc[mi][np*2+1], afl[mi], bf[2], bf[3]);
            }
        }
    }
}

#define ZERO_ACC(acc)                                                         \
    _Pragma("unroll") for (int mi = 0; mi < 2; ++mi)                          \
    _Pragma("unroll") for (int ni = 0; ni < 8; ++ni)                          \
    _Pragma("unroll") for (int q = 0; q < 4; ++q) acc[mi][ni][q] = 0.0f;

// 3-buffer pipeline, one barrier per stage, prefetch depth 2.
#define MAINLOOP(STAGE_CALL)                                                  \
    STAGE_CALL(0, 0); CPA_COMMIT();                                           \
    STAGE_CALL(1, 1); CPA_COMMIT();                                           \
    for (int s = 0; s < 8; ++s) {                                             \
        if (s == 7) { CPA_WAIT(0); } else { CPA_WAIT(1); }                    \
        __syncthreads();                                                      \
        if (s < 6) { STAGE_CALL((s + 2) % 3, s + 2); CPA_COMMIT(); }          \
        compute_chunk(acc, sb + (s % 3) * BUF_SZ, warpM, warpN, lane);        \
    }

// ---------------------------------------------------------------------------
// Prep: fp32 -> fp16 pair (dest 0/1) or fp16 single (dest 2/3)
// ---------------------------------------------------------------------------
__global__ void k_prep(const float* __restrict__ src, int dest, size_t cnt)
{
    size_t i = ((size_t)blockIdx.x * 256 + threadIdx.x) * 8;
    if (i >= cnt) return;
    float4 v0 = *reinterpret_cast<const float4*>(src + i);
    float4 v1 = *reinterpret_cast<const float4*>(src + i + 4);
    float x[8] = {v0.x, v0.y, v0.z, v0.w, v1.x, v1.y, v1.z, v1.w};
    if (dest >= 2) {
        __half* d = g_W + (dest == 2 ? 0ull : WSZ);
        u32 o[4];
#pragma unroll
        for (int j = 0; j < 4; ++j) {
            __half2 h = __floats2half2_rn(x[2*j], x[2*j+1]);
            o[j] = *reinterpret_cast<u32*>(&h);
        }
        *reinterpret_cast<uint4*>(d + i) = make_uint4(o[0], o[1], o[2], o[3]);
    } else {
        __half* dh = dest ? g_L2h : g_L1h;
        __half* dl = dest ? g_L2l : g_L1l;
        u32 oh[4], ol[4];
#pragma unroll
        for (int j = 0; j < 4; ++j) {
            __half h0 = __float2half_rn(x[2*j]);
            __half h1 = __float2half_rn(x[2*j+1]);
            __half l0 = __float2half_rn(x[2*j]   - __half2float(h0));
            __half l1 = __float2half_rn(x[2*j+1] - __half2float(h1));
            __half2 hh = __halves2half2(h0, h1), lll = __halves2half2(l0, l1);
            oh[j] = *reinterpret_cast<u32*>(&hh);
            ol[j] = *reinterpret_cast<u32*>(&lll);
        }
        *reinterpret_cast<uint4*>(dh + i) = make_uint4(oh[0], oh[1], oh[2], oh[3]);
        *reinterpret_cast<uint4*>(dl + i) = make_uint4(ol[0], ol[1], ol[2], ol[3]);
    }
}

// transpose + fp16: W3T[d][c] = W3[c][d]
__global__ void k_prep_w3(const float* __restrict__ W3)
{
    __shared__ float t[32][33];
    int bx = blockIdx.x * 32, by = blockIdx.y * 32;
    t[threadIdx.y][threadIdx.x] = W3[(size_t)(by + threadIdx.y) * 256 + bx + threadIdx.x];
    __syncthreads();
    g_W3T[(size_t)(bx + threadIdx.y) * 256 + by + threadIdx.x] =
        __float2half_rn(t[threadIdx.x][threadIdx.y]);
}

// ---------------------------------------------------------------------------
// K1: grid (16 mt, 514 nt, 2 w). D[128 m][128 bc], K=256 over a -> X fp16.
// ---------------------------------------------------------------------------
__global__ void __launch_bounds__(256, 2)
k1_gemm()
{
    extern __shared__ char smem[];
    const int tid = threadIdx.x, lane = tid & 31, wid = tid >> 5;
    const int warpM = wid & 3, warpN = wid >> 2;
    const int mBase = blockIdx.x * 128;
    const size_t n0 = (size_t)blockIdx.y * 128;
    const int w = blockIdx.z;
    const __half* WP  = g_W + (size_t)w * WSZ + n0;
    __half* XP        = g_X + (size_t)w * XSZ;
    const __half* AhP = g_L1h + (size_t)mBase * 256;
    const __half* AlP = g_L1l + (size_t)mBase * 256;
    const u32 sb = smem_u32(smem);

    float acc[2][8][4];
    ZERO_ACC(acc)

#define K1_STAGE(buf, s) stage_tiles(sb, buf, tid, AhP, AlP, 256, WP, 65792, (s) * 32)
    MAINLOOP(K1_STAGE)
#undef K1_STAGE

    const int gq = lane >> 2, t = lane & 3;
#pragma unroll
    for (int mi = 0; mi < 2; ++mi) {
        int row = mBase + warpM * 32 + mi * 16 + gq;
#pragma unroll
        for (int ni = 0; ni < 8; ++ni) {
            int colL = warpN * 64 + ni * 8 + t * 2;
            __half2 b2 = *reinterpret_cast<const __half2*>(WP + 256ull * 65792 + colL);
            float b0 = __half2float(__low2half(b2));
            float b1 = __half2float(__high2half(b2));
            size_t col = n0 + colL;
            __half2 o0 = __floats2half2_rn(acc[mi][ni][0] + b0, acc[mi][ni][1] + b1);
            __half2 o1 = __floats2half2_rn(acc[mi][ni][2] + b0, acc[mi][ni][3] + b1);
            *reinterpret_cast<__half2*>(XP + (size_t)row * 65792 + col) = o0;
            *reinterpret_cast<__half2*>(XP + (size_t)(row + 8) * 65792 + col) = o1;
        }
    }
}

// ---------------------------------------------------------------------------
// K2: grid (4 = mt + 2*nt, 2048 m, 2 w). D[128 j][128 c], K=256 over b.
// w=0: g_Af = (res+bias)*h1 fp32;  w=1: g_Ah/g_Al = pair((res+bias)*h2).
// ---------------------------------------------------------------------------
__global__ void __launch_bounds__(256, 2)
k2_gemm(const float* __restrict__ h1, const float* __restrict__ h2)
{
    extern __shared__ char smem[];
    const int tid = threadIdx.x, lane = tid & 31, wid = tid >> 5;
    const int warpM = wid & 3, warpN = wid >> 2;
    const int mt = blockIdx.x & 1, nt = blockIdx.x >> 1;
    const int m = blockIdx.y, w = blockIdx.z;
    const size_t n0 = (size_t)nt * 128;
    const __half* XP  = g_X + (size_t)w * XSZ + (size_t)m * 65792 + n0;
    const __half* AhP = g_L2h + ((size_t)(m >> 8) * 256 + mt * 128) * 256;
    const __half* AlP = g_L2l + ((size_t)(m >> 8) * 256 + mt * 128) * 256;
    const u32 sb = smem_u32(smem);
    float* hsm = reinterpret_cast<float*>(smem + SM_H);

    if (tid < 128)
        hsm[tid] = (w ? h2 : h1)[(size_t)m * 256 + n0 + tid];

    float acc[2][8][4];
    ZERO_ACC(acc)

#define K2_STAGE(buf, s) stage_tiles(sb, buf, tid, AhP, AlP, 256, XP, 256, (s) * 32)
    MAINLOOP(K2_STAGE)
#undef K2_STAGE

    const int gq = lane >> 2, t = lane & 3;
#pragma unroll
    for (int mi = 0; mi < 2; ++mi) {
        int row = mt * 128 + warpM * 32 + mi * 16 + gq;
#pragma unroll
        for (int ni = 0; ni < 8; ++ni) {
            int colL = warpN * 64 + ni * 8 + t * 2;
            __half2 b2 = *reinterpret_cast<const __half2*>(XP + 256ull * 256 + colL);
            float b0 = __half2float(__low2half(b2));
            float b1 = __half2float(__high2half(b2));
            float s0 = hsm[colL], s1 = hsm[colL + 1];
            size_t col = n0 + colL;
            float v00 = (acc[mi][ni][0] + b0) * s0, v01 = (acc[mi][ni][1] + b1) * s1;
            float v10 = (acc[mi][ni][2] + b0) * s0, v11 = (acc[mi][ni][3] + b1) * s1;
            if (w == 0) {
                float* p = g_Af + (size_t)m * 65536 + (size_t)row * 256 + col;
                *reinterpret_cast<float2*>(p) = make_float2(v00, v01);
                *reinterpret_cast<float2*>(p + 8ull * 256) = make_float2(v10, v11);
            } else {
                size_t o = (size_t)m * 65536 + (size_t)row * 256 + col;
                __half h0 = __float2half_rn(v00), h1h = __float2half_rn(v01);
                __half l0 = __float2half_rn(v00 - __half2float(h0));
                __half l1 = __float2half_rn(v01 - __half2float(h1h));
                *reinterpret_cast<__half2*>(g_Ah + o) = __halves2half2(h0, h1h);
                *reinterpret_cast<__half2*>(g_Al + o) = __halves2half2(l0, l1);
                h0 = __float2half_rn(v10); h1h = __float2half_rn(v11);
                l0 = __float2half_rn(v10 - __half2float(h0));
                l1 = __float2half_rn(v11 - __half2float(h1h));
                *reinterpret_cast<__half2*>(g_Ah + o + 8ull * 256) = __halves2half2(h0, h1h);
                *reinterpret_cast<__half2*>(g_Al + o + 8ull * 256) = __halves2half2(l0, l1);
            }
        }
    }
}

// ---------------------------------------------------------------------------
// K3: grid (2 jt, 2048 m). Two c-halves of T[128 j][128 c], K=256 over d,
// fused Af*T reduction -> out.
// ---------------------------------------------------------------------------
__global__ void __launch_bounds__(256, 2)
k3_final(float* __restrict__ out)
{
    extern __shared__ char smem[];
    const int tid = threadIdx.x, lane = tid & 31, wid = tid >> 5;
    const int warpM = wid & 3, warpN = wid >> 2;
    const int jt = blockIdx.x, m = blockIdx.y;
    const __half* AhP = g_Ah + (size_t)m * 65536 + (size_t)jt * 128 * 256;
    const __half* AlP = g_Al + (size_t)m * 65536 + (size_t)jt * 128 * 256;
    const float* AfP  = g_Af + (size_t)m * 65536 + (size_t)jt * 128 * 256;
    const u32 sb = smem_u32(smem);
    float* red = reinterpret_cast<float*>(smem + SM_RED);
    const int gq = lane >> 2, t = lane & 3;

    float rs[2][2] = {{0.0f, 0.0f}, {0.0f, 0.0f}};

    for (int ct = 0; ct < 2; ++ct) {
        const __half* BP = g_W3T + ct * 128;

        float acc[2][8][4];
        ZERO_ACC(acc)

        __syncthreads();   // all warps done reading smem bufs from previous half

#define K3_STAGE(buf, s) stage_tiles(sb, buf, tid, AhP, AlP, 256, BP, 256, (s) * 32)
        MAINLOOP(K3_STAGE)
#undef K3_STAGE

#pragma unroll
        for (int mi = 0; mi < 2; ++mi) {
            int j0 = warpM * 32 + mi * 16 + gq;
#pragma unroll
            for (int ni = 0; ni < 8; ++ni) {
                int c = ct * 128 + warpN * 64 + ni * 8 + t * 2;
                const float* ap = AfP + (size_t)j0 * 256 + c;
                float2 a0 = *reinterpret_cast<const float2*>(ap);
                float2 a1 = *reinterpret_cast<const float2*>(ap + 8ull * 256);
                rs[mi][0] += a0.x * acc[mi][ni][0] + a0.y * acc[mi][ni][1];
                rs[mi][1] += a1.x * acc[mi][ni][2] + a1.y * acc[mi][ni][3];
            }
        }
    }

#pragma unroll
    for (int mi = 0; mi < 2; ++mi)
#pragma unroll
        for (int h = 0; h < 2; ++h) {
            rs[mi][h] += __shfl_xor_sync(0xffffffffu, rs[mi][h], 1);
            rs[mi][h] += __shfl_xor_sync(0xffffffffu, rs[mi][h], 2);
        }
    __syncthreads();
    if (t == 0) {
#pragma unroll
        for (int mi = 0; mi < 2; ++mi) {
            red[warpN * 128 + warpM * 32 + mi * 16 + gq]     = rs[mi][0];
            red[warpN * 128 + warpM * 32 + mi * 16 + 8 + gq] = rs[mi][1];
        }
    }
    __syncthreads();
    if (tid < 128)
        out[(size_t)m * 256 + jt * 128 + tid] = red[tid] + red[128 + tid];
}

// ---------------------------------------------------------------------------
extern "C" void kernel_launch(void* const* d_in, const int* in_sizes, int n_in,
                              void* d_out, int out_size)
{
    const float* layer1 = (const float*)d_in[0];
    const float* layer2 = (const float*)d_in[1];
    const float* h1     = (const float*)d_in[2];
    const float* h2     = (const float*)d_in[3];
    const float* W1     = (const float*)d_in[4];
    const float* W2     = (const float*)d_in[5];
    const float* W3     = (const float*)d_in[6];
    float* out = (float*)d_out;

    cudaFuncSetAttribute(k1_gemm,  cudaFuncAttributeMaxDynamicSharedMemorySize, SMEM_SZ);
    cudaFuncSetAttribute(k2_gemm,  cudaFuncAttributeMaxDynamicSharedMemorySize, SMEM_SZ);
    cudaFuncSetAttribute(k3_final, cudaFuncAttributeMaxDynamicSharedMemorySize, SMEM_SZ);

    k_prep<<<256,  256>>>(layer1, 0, 524288ull);
    k_prep<<<256,  256>>>(layer2, 1, 524288ull);
    k_prep<<<8257, 256>>>(W1, 2, WSZ);
    k_prep<<<8257, 256>>>(W2, 3, WSZ);
    k_prep_w3<<<dim3(8, 8), dim3(32, 32)>>>(W3);

    k1_gemm<<<dim3(16, 514, 2), 256, SMEM_SZ>>>();
    k2_gemm<<<dim3(4, 2048, 2), 256, SMEM_SZ>>>(h1, h2);
    k3_final<<<dim3(2, 2048),   256, SMEM_SZ>>>(out);
}

// round 11
// speedup vs baseline: 5.1236x; 1.3027x over previous
#include <cuda_runtime.h>
#include <cuda_fp16.h>
#include <cstdint>

typedef uint32_t u32;

// ---------------------------------------------------------------------------
// Triaffine via 3 GEMM stages on tensor cores (mma.sync m16n8k16 fp16, fp32
// accum).
//  K1: X{1,2} = l1(fp16) @ W{1,2}(fp16) + bias      (1-term mma)
//  K2: A_l = l2(fp16) @ X1 + bias, *h1 -> fp32
//      A_r = l2(fp16) @ X2 + bias, *h2 -> fp16 hi/lo pair
//  K3: T = A_r(pair) @ W3T(fp16) (2-term);  out[j] = sum_c A_l[j,c]*T[j,c]
// Pipeline: cp.async, 4 smem buffers (depth-3 prefetch), XOR swizzle,
// one __syncthreads per BK=32 stage, 2 CTAs/SM.
// ---------------------------------------------------------------------------

#define WSZ 16908544ull              // 257*65792
#define XSZ (2048ull*65792)

__device__ __half g_L1[2048ull*256], g_L2[2048ull*256];
__device__ __half g_W[2ull*WSZ];                   // W1 | W2 (fp16)
__device__ __half g_X[2ull*XSZ];                   // X1 | X2 (fp16)
__device__ float  g_Af[2048ull*65536];             // h1-scaled A_l (fp32)
__device__ __half g_Ah[2048ull*65536], g_Al[2048ull*65536];  // h2-scaled A_r pair
__device__ __half g_W3T[256*256];                  // W3T[d][c] (fp16)

// K1/K2 buffer: [A 8192 | B 8192] x 4;  K3 buffer: [Ah 8192 | Al 8192 | B 8192] x 4
#define BUF12   16384
#define BUF3    24576
#define SM_H12  65536
#define SMEM12  (SM_H12 + 512)       // 66048
#define SM_RED3 98304
#define SMEM3   (SM_RED3 + 1024)     // 99328

// ---------------- PTX helpers ----------------
__device__ __forceinline__ u32 smem_u32(const void* p) {
    u32 a;
    asm("{ .reg .u64 t; cvta.to.shared.u64 t, %1; cvt.u32.u64 %0, t; }" : "=r"(a) : "l"(p));
    return a;
}
__device__ __forceinline__ void cpa16(u32 s, const void* g) {
    asm volatile("cp.async.cg.shared.global [%0], [%1], 16;" :: "r"(s), "l"(g));
}
#define CPA_COMMIT() asm volatile("cp.async.commit_group;" ::: "memory")
#define CPA_WAIT(n)  asm volatile("cp.async.wait_group %0;" :: "n"(n) : "memory")

__device__ __forceinline__ void ldm_x4(u32 addr, u32 r[4]) {
    asm volatile("ldmatrix.sync.aligned.m8n8.x4.shared.b16 {%0,%1,%2,%3}, [%4];"
        : "=r"(r[0]), "=r"(r[1]), "=r"(r[2]), "=r"(r[3]) : "r"(addr));
}
__device__ __forceinline__ void ldm_x4_t(u32 addr, u32 r[4]) {
    asm volatile("ldmatrix.sync.aligned.m8n8.x4.trans.shared.b16 {%0,%1,%2,%3}, [%4];"
        : "=r"(r[0]), "=r"(r[1]), "=r"(r[2]), "=r"(r[3]) : "r"(addr));
}
__device__ __forceinline__ void mma_f16(float c[4], const u32 a[4], u32 b0, u32 b1) {
    asm volatile("mma.sync.aligned.m16n8k16.row.col.f32.f16.f16.f32 "
        "{%0,%1,%2,%3}, {%4,%5,%6,%7}, {%8,%9}, {%0,%1,%2,%3};"
        : "+f"(c[0]), "+f"(c[1]), "+f"(c[2]), "+f"(c[3])
        : "r"(a[0]), "r"(a[1]), "r"(a[2]), "r"(a[3]), "r"(b0), "r"(b1));
}

// XOR-swizzled addresses (chunk = 16B unit within a row)
__device__ __forceinline__ u32 sw_a(u32 base, int row, int c) {      // 64B rows
    return base + row * 64 + ((c ^ ((row >> 1) & 3)) << 4);
}
__device__ __forceinline__ u32 sw_b(u32 base, int row, int c) {      // 256B rows
    return base + row * 256 + ((c ^ (row & 7)) << 4);
}

// ---------------------------------------------------------------------------
// Staging (BK=32): single-A (K1/K2) and pair-A (K3) variants.
// ---------------------------------------------------------------------------
__device__ __forceinline__ void stage_s(u32 sb, int buf, int tid,
    const __half* __restrict__ a, size_t apitch,
    const __half* __restrict__ b, size_t bpitch, int k0)
{
    const int arow = tid >> 1, ac = tid & 1;
    const int brow = tid >> 3, bc = tid & 7;
    const u32 base = sb + buf * BUF12;
    const __half* g = a + (size_t)arow * apitch + k0 + ac * 16;
    cpa16(sw_a(base, arow, ac * 2), g);
    cpa16(sw_a(base, arow, ac * 2 + 1), g + 8);
    g = b + (size_t)(k0 + brow) * bpitch + bc * 16;
    cpa16(sw_b(base + 8192, brow, bc * 2), g);
    cpa16(sw_b(base + 8192, brow, bc * 2 + 1), g + 8);
}
__device__ __forceinline__ void stage_p(u32 sb, int buf, int tid,
    const __half* __restrict__ ah, const __half* __restrict__ al, size_t apitch,
    const __half* __restrict__ b, size_t bpitch, int k0)
{
    const int arow = tid >> 1, ac = tid & 1;
    const int brow = tid >> 3, bc = tid & 7;
    const u32 base = sb + buf * BUF3;
    const __half* g = ah + (size_t)arow * apitch + k0 + ac * 16;
    cpa16(sw_a(base, arow, ac * 2), g);
    cpa16(sw_a(base, arow, ac * 2 + 1), g + 8);
    g = al + (size_t)arow * apitch + k0 + ac * 16;
    cpa16(sw_a(base + 8192, arow, ac * 2), g);
    cpa16(sw_a(base + 8192, arow, ac * 2 + 1), g + 8);
    g = b + (size_t)(k0 + brow) * bpitch + bc * 16;
    cpa16(sw_b(base + 16384, brow, bc * 2), g);
    cpa16(sw_b(base + 16384, brow, bc * 2 + 1), g + 8);
}

// ---------------------------------------------------------------------------
// Warp tile 32x64 compute over one BK=32 chunk.
// single-A: 32 mma per warp;  pair-A: 64 mma per warp.
// ---------------------------------------------------------------------------
__device__ __forceinline__ void compute_s(float acc[2][8][4],
        u32 base, int warpM, int warpN, int lane)
{
    const int lr = lane & 15, lh = lane >> 4;
#pragma unroll
    for (int kk = 0; kk < 2; ++kk) {
        u32 af[2][4];
#pragma unroll
        for (int mi = 0; mi < 2; ++mi)
            ldm_x4(sw_a(base, warpM * 32 + mi * 16 + lr, kk * 2 + lh), af[mi]);
#pragma unroll
        for (int np = 0; np < 4; ++np) {
            u32 bf[4];
            ldm_x4_t(sw_b(base + 8192, kk * 16 + lr, warpN * 8 + np * 2 + lh), bf);
#pragma unroll
            for (int mi = 0; mi < 2; ++mi) {
                mma_f16(acc[mi][np*2],   af[mi], bf[0], bf[1]);
                mma_f16(acc[mi][np*2+1], af[mi], bf[2], bf[3]);
            }
        }
    }
}
__device__ __forceinline__ void compute_p(float acc[2][8][4],
        u32 base, int warpM, int warpN, int lane)
{
    const int lr = lane & 15, lh = lane >> 4;
#pragma unroll
    for (int kk = 0; kk < 2; ++kk) {
        u32 afh[2][4], afl[2][4];
#pragma unroll
        for (int mi = 0; mi < 2; ++mi) {
            int row = warpM * 32 + mi * 16 + lr;
            ldm_x4(sw_a(base, row, kk * 2 + lh), afh[mi]);
            ldm_x4(sw_a(base + 8192, row, kk * 2 + lh), afl[mi]);
        }
#pragma unroll
        for (int np = 0; np < 4; ++np) {
            u32 bf[4];
            ldm_x4_t(sw_b(base + 16384, kk * 16 + lr, warpN * 8 + np * 2 + lh), bf);
#pragma unroll
            for (int mi = 0; mi < 2; ++mi) {
                mma_f16(acc[mi][np*2],   afh[mi], bf[0], bf[1]);
                mma_f16(acc[mi][np*2],   afl[mi], bf[0], bf[1]);
                mma_f16(acc[mi][np*2+1], afh[mi], bf[2], bf[3]);
                mma_f16(acc[mi][np*2+1], afl[mi], bf[2], bf[3]);
            }
        }
    }
}

#define ZERO_ACC(acc)                                                         \
    _Pragma("unroll") for (int mi = 0; mi < 2; ++mi)                          \
    _Pragma("unroll") for (int ni = 0; ni < 8; ++ni)                          \
    _Pragma("unroll") for (int q = 0; q < 4; ++q) acc[mi][ni][q] = 0.0f;

// 4-buffer pipeline, prefetch depth 3, one barrier per stage.
#define MAINLOOP(STAGE_CALL, COMPUTE, BUFSZ)                                  \
    STAGE_CALL(0, 0); CPA_COMMIT();                                           \
    STAGE_CALL(1, 1); CPA_COMMIT();                                           \
    STAGE_CALL(2, 2); CPA_COMMIT();                                           \
    for (int s = 0; s < 8; ++s) {                                             \
        if (s <= 5) { CPA_WAIT(2); } else if (s == 6) { CPA_WAIT(1); }        \
        else { CPA_WAIT(0); }                                                 \
        __syncthreads();                                                      \
        if (s < 5) { STAGE_CALL((s + 3) & 3, s + 3); CPA_COMMIT(); }          \
        COMPUTE(acc, sb + (s & 3) * (BUFSZ), warpM, warpN, lane);             \
    }

// ---------------------------------------------------------------------------
// Prep: fp32 -> fp16 (dest: 0 L1, 1 L2, 2 W1, 3 W2)
// ---------------------------------------------------------------------------
__global__ void k_prep(const float* __restrict__ src, int dest, size_t cnt)
{
    size_t i = ((size_t)blockIdx.x * 256 + threadIdx.x) * 8;
    if (i >= cnt) return;
    __half* d;
    switch (dest) {
        case 0:  d = g_L1; break;
        case 1:  d = g_L2; break;
        case 2:  d = g_W;  break;
        default: d = g_W + WSZ; break;
    }
    float4 v0 = *reinterpret_cast<const float4*>(src + i);
    float4 v1 = *reinterpret_cast<const float4*>(src + i + 4);
    float x[8] = {v0.x, v0.y, v0.z, v0.w, v1.x, v1.y, v1.z, v1.w};
    u32 o[4];
#pragma unroll
    for (int j = 0; j < 4; ++j) {
        __half2 h = __floats2half2_rn(x[2*j], x[2*j+1]);
        o[j] = *reinterpret_cast<u32*>(&h);
    }
    *reinterpret_cast<uint4*>(d + i) = make_uint4(o[0], o[1], o[2], o[3]);
}

// transpose + fp16: W3T[d][c] = W3[c][d]
__global__ void k_prep_w3(const float* __restrict__ W3)
{
    __shared__ float t[32][33];
    int bx = blockIdx.x * 32, by = blockIdx.y * 32;
    t[threadIdx.y][threadIdx.x] = W3[(size_t)(by + threadIdx.y) * 256 + bx + threadIdx.x];
    __syncthreads();
    g_W3T[(size_t)(bx + threadIdx.y) * 256 + by + threadIdx.x] =
        __float2half_rn(t[threadIdx.x][threadIdx.y]);
}

// ---------------------------------------------------------------------------
// K1: grid (16 mt, 514 nt, 2 w). D[128 m][128 bc], K=256 over a -> X fp16.
// ---------------------------------------------------------------------------
__global__ void __launch_bounds__(256, 2)
k1_gemm()
{
    extern __shared__ char smem[];
    const int tid = threadIdx.x, lane = tid & 31, wid = tid >> 5;
    const int warpM = wid & 3, warpN = wid >> 2;
    const int mBase = blockIdx.x * 128;
    const size_t n0 = (size_t)blockIdx.y * 128;
    const int w = blockIdx.z;
    const __half* WP = g_W + (size_t)w * WSZ + n0;
    __half* XP       = g_X + (size_t)w * XSZ;
    const __half* AP = g_L1 + (size_t)mBase * 256;
    const u32 sb = smem_u32(smem);

    float acc[2][8][4];
    ZERO_ACC(acc)

#define K1_STAGE(buf, s) stage_s(sb, buf, tid, AP, 256, WP, 65792, (s) * 32)
    MAINLOOP(K1_STAGE, compute_s, BUF12)
#undef K1_STAGE

    const int gq = lane >> 2, t = lane & 3;
#pragma unroll
    for (int mi = 0; mi < 2; ++mi) {
        int row = mBase + warpM * 32 + mi * 16 + gq;
#pragma unroll
        for (int ni = 0; ni < 8; ++ni) {
            int colL = warpN * 64 + ni * 8 + t * 2;
            __half2 b2 = *reinterpret_cast<const __half2*>(WP + 256ull * 65792 + colL);
            float b0 = __half2float(__low2half(b2));
            float b1 = __half2float(__high2half(b2));
            size_t col = n0 + colL;
            __half2 o0 = __floats2half2_rn(acc[mi][ni][0] + b0, acc[mi][ni][1] + b1);
            __half2 o1 = __floats2half2_rn(acc[mi][ni][2] + b0, acc[mi][ni][3] + b1);
            *reinterpret_cast<__half2*>(XP + (size_t)row * 65792 + col) = o0;
            *reinterpret_cast<__half2*>(XP + (size_t)(row + 8) * 65792 + col) = o1;
        }
    }
}

// ---------------------------------------------------------------------------
// K2: grid (4 = mt + 2*nt, 2048 m, 2 w). D[128 j][128 c], K=256 over b.
// w=0: g_Af = (res+bias)*h1 fp32;  w=1: g_Ah/g_Al = pair((res+bias)*h2).
// ---------------------------------------------------------------------------
__global__ void __launch_bounds__(256, 2)
k2_gemm(const float* __restrict__ h1, const float* __restrict__ h2)
{
    extern __shared__ char smem[];
    const int tid = threadIdx.x, lane = tid & 31, wid = tid >> 5;
    const int warpM = wid & 3, warpN = wid >> 2;
    const int mt = blockIdx.x & 1, nt = blockIdx.x >> 1;
    const int m = blockIdx.y, w = blockIdx.z;
    const size_t n0 = (size_t)nt * 128;
    const __half* XP = g_X + (size_t)w * XSZ + (size_t)m * 65792 + n0;
    const __half* AP = g_L2 + ((size_t)(m >> 8) * 256 + mt * 128) * 256;
    const u32 sb = smem_u32(smem);
    float* hsm = reinterpret_cast<float*>(smem + SM_H12);

    if (tid < 128)
        hsm[tid] = (w ? h2 : h1)[(size_t)m * 256 + n0 + tid];

    float acc[2][8][4];
    ZERO_ACC(acc)

#define K2_STAGE(buf, s) stage_s(sb, buf, tid, AP, 256, XP, 256, (s) * 32)
    MAINLOOP(K2_STAGE, compute_s, BUF12)
#undef K2_STAGE

    const int gq = lane >> 2, t = lane & 3;
#pragma unroll
    for (int mi = 0; mi < 2; ++mi) {
        int row = mt * 128 + warpM * 32 + mi * 16 + gq;
#pragma unroll
        for (int ni = 0; ni < 8; ++ni) {
            int colL = warpN * 64 + ni * 8 + t * 2;
            __half2 b2 = *reinterpret_cast<const __half2*>(XP + 256ull * 256 + colL);
            float b0 = __half2float(__low2half(b2));
            float b1 = __half2float(__high2half(b2));
            float s0 = hsm[colL], s1 = hsm[colL + 1];
            size_t col = n0 + colL;
            float v00 = (acc[mi][ni][0] + b0) * s0, v01 = (acc[mi][ni][1] + b1) * s1;
            float v10 = (acc[mi][ni][2] + b0) * s0, v11 = (acc[mi][ni][3] + b1) * s1;
            if (w == 0) {
                float* p = g_Af + (size_t)m * 65536 + (size_t)row * 256 + col;
                *reinterpret_cast<float2*>(p) = make_float2(v00, v01);
                *reinterpret_cast<float2*>(p + 8ull * 256) = make_float2(v10, v11);
            } else {
                size_t o = (size_t)m * 65536 + (size_t)row * 256 + col;
                __half h0 = __float2half_rn(v00), h1h = __float2half_rn(v01);
                __half l0 = __float2half_rn(v00 - __half2float(h0));
                __half l1 = __float2half_rn(v01 - __half2float(h1h));
                *reinterpret_cast<__half2*>(g_Ah + o) = __halves2half2(h0, h1h);
                *reinterpret_cast<__half2*>(g_Al + o) = __halves2half2(l0, l1);
                h0 = __float2half_rn(v10); h1h = __float2half_rn(v11);
                l0 = __float2half_rn(v10 - __half2float(h0));
                l1 = __float2half_rn(v11 - __half2float(h1h));
                *reinterpret_cast<__half2*>(g_Ah + o + 8ull * 256) = __halves2half2(h0, h1h);
                *reinterpret_cast<__half2*>(g_Al + o + 8ull * 256) = __halves2half2(l0, l1);
            }
        }
    }
}

// ---------------------------------------------------------------------------
// K3: grid (2 jt, 2048 m). Two c-halves of T[128 j][128 c], K=256 over d,
// fused Af*T reduction -> out.
// ---------------------------------------------------------------------------
__global__ void __launch_bounds__(256, 2)
k3_final(float* __restrict__ out)
{
    extern __shared__ char smem[];
    const int tid = threadIdx.x, lane = tid & 31, wid = tid >> 5;
    const int warpM = wid & 3, warpN = wid >> 2;
    const int jt = blockIdx.x, m = blockIdx.y;
    const __half* AhP = g_Ah + (size_t)m * 65536 + (size_t)jt * 128 * 256;
    const __half* AlP = g_Al + (size_t)m * 65536 + (size_t)jt * 128 * 256;
    const float* AfP  = g_Af + (size_t)m * 65536 + (size_t)jt * 128 * 256;
    const u32 sb = smem_u32(smem);
    float* red = reinterpret_cast<float*>(smem + SM_RED3);
    const int gq = lane >> 2, t = lane & 3;

    float rs[2][2] = {{0.0f, 0.0f}, {0.0f, 0.0f}};

    for (int ct = 0; ct < 2; ++ct) {
        const __half* BP = g_W3T + ct * 128;

        float acc[2][8][4];
        ZERO_ACC(acc)

        __syncthreads();   // prior half's buffer reads complete

#define K3_STAGE(buf, s) stage_p(sb, buf, tid, AhP, AlP, 256, BP, 256, (s) * 32)
        MAINLOOP(K3_STAGE, compute_p, BUF3)
#undef K3_STAGE

#pragma unroll
        for (int mi = 0; mi < 2; ++mi) {
            int j0 = warpM * 32 + mi * 16 + gq;
#pragma unroll
            for (int ni = 0; ni < 8; ++ni) {
                int c = ct * 128 + warpN * 64 + ni * 8 + t * 2;
                const float* ap = AfP + (size_t)j0 * 256 + c;
                float2 a0 = *reinterpret_cast<const float2*>(ap);
                float2 a1 = *reinterpret_cast<const float2*>(ap + 8ull * 256);
                rs[mi][0] += a0.x * acc[mi][ni][0] + a0.y * acc[mi][ni][1];
                rs[mi][1] += a1.x * acc[mi][ni][2] + a1.y * acc[mi][ni][3];
            }
        }
    }

#pragma unroll
    for (int mi = 0; mi < 2; ++mi)
#pragma unroll
        for (int h = 0; h < 2; ++h) {
            rs[mi][h] += __shfl_xor_sync(0xffffffffu, rs[mi][h], 1);
            rs[mi][h] += __shfl_xor_sync(0xffffffffu, rs[mi][h], 2);
        }
    __syncthreads();
    if (t == 0) {
#pragma unroll
        for (int mi = 0; mi < 2; ++mi) {
            red[warpN * 128 + warpM * 32 + mi * 16 + gq]     = rs[mi][0];
            red[warpN * 128 + warpM * 32 + mi * 16 + 8 + gq] = rs[mi][1];
        }
    }
    __syncthreads();
    if (tid < 128)
        out[(size_t)m * 256 + jt * 128 + tid] = red[tid] + red[128 + tid];
}

// ---------------------------------------------------------------------------
extern "C" void kernel_launch(void* const* d_in, const int* in_sizes, int n_in,
                              void* d_out, int out_size)
{
    const float* layer1 = (const float*)d_in[0];
    const float* layer2 = (const float*)d_in[1];
    const float* h1     = (const float*)d_in[2];
    const float* h2     = (const float*)d_in[3];
    const float* W1     = (const float*)d_in[4];
    const float* W2     = (const float*)d_in[5];
    const float* W3     = (const float*)d_in[6];
    float* out = (float*)d_out;

    cudaFuncSetAttribute(k1_gemm,  cudaFuncAttributeMaxDynamicSharedMemorySize, SMEM12);
    cudaFuncSetAttribute(k2_gemm,  cudaFuncAttributeMaxDynamicSharedMemorySize, SMEM12);
    cudaFuncSetAttribute(k3_final, cudaFuncAttributeMaxDynamicSharedMemorySize, SMEM3);

    k_prep<<<256,  256>>>(layer1, 0, 524288ull);
    k_prep<<<256,  256>>>(layer2, 1, 524288ull);
    k_prep<<<8257, 256>>>(W1, 2, WSZ);
    k_prep<<<8257, 256>>>(W2, 3, WSZ);
    k_prep_w3<<<dim3(8, 8), dim3(32, 32)>>>(W3);

    k1_gemm<<<dim3(16, 514, 2), 256, SMEM12>>>();
    k2_gemm<<<dim3(4, 2048, 2), 256, SMEM12>>>(h1, h2);
    k3_final<<<dim3(2, 2048),   256, SMEM3>>>(out);
}

// round 12
// speedup vs baseline: 6.1545x; 1.2012x over previous
#include <cuda_runtime.h>
#include <cuda_fp16.h>
#include <cstdint>

typedef uint32_t u32;

// ---------------------------------------------------------------------------
// Triaffine, tensor-core fp16 mma (fp32 accum), 2 GEMM kernels:
//  K1: X{1,2} = l1(fp16) @ W{1,2}(fp16) + bias              -> g_X fp16
//  K23 (fused, per (m, 128-j tile)):
//    s1: A_r = l2 @ X2 + bias, *h2  -> smem pair (fp16 hi/lo)
//    s2: T   = pair @ W3T (2-term), *h1 -> smem fp32 (overwrites pair)
//    s3: A_l = l2 @ X1 + bias;  out[j] = sum_c A_l[j,c] * T[j,c]
// Kills the 2.1 GB g_Af/g_Ah/g_Al scratch round-trip of the unfused version.
// ---------------------------------------------------------------------------

#define WSZ 16908544ull              // 257*65792
#define XSZ (2048ull*65792)

__device__ __half g_L1[2048ull*256], g_L2[2048ull*256];
__device__ __half g_W[2ull*WSZ];                   // W1 | W2 (fp16)
__device__ __half g_X[2ull*XSZ];                   // X1 | X2 (fp16)
__device__ __half g_W3T[256*256];                  // W3T[d][c] (fp16)

// ---- K1 smem (256 threads, 2 CTA/SM): [A 8192 | B 8192] x 4 ----
#define BUF12   16384
#define SMEM12  65536

// ---- K23 smem (512 threads, 1 CTA/SM) ----
#define FBUF    24576                // [A 8192 | B 16384] x 3
#define FSM_P   73728                // pair: hi 64KB | lo 64KB; T overlaps (133120B)
#define FSM_H   206848               // h1 1KB | h2 1KB
#define FSM_RED 208896               // 4 x 128 floats
#define FSMEM   210944

// ---------------- PTX helpers ----------------
__device__ __forceinline__ u32 smem_u32(const void* p) {
    u32 a;
    asm("{ .reg .u64 t; cvta.to.shared.u64 t, %1; cvt.u32.u64 %0, t; }" : "=r"(a) : "l"(p));
    return a;
}
__device__ __forceinline__ void cpa16(u32 s, const void* g) {
    asm volatile("cp.async.cg.shared.global [%0], [%1], 16;" :: "r"(s), "l"(g));
}
#define CPA_COMMIT() asm volatile("cp.async.commit_group;" ::: "memory")
#define CPA_WAIT(n)  asm volatile("cp.async.wait_group %0;" :: "n"(n) : "memory")

__device__ __forceinline__ void ldm_x4(u32 addr, u32 r[4]) {
    asm volatile("ldmatrix.sync.aligned.m8n8.x4.shared.b16 {%0,%1,%2,%3}, [%4];"
        : "=r"(r[0]), "=r"(r[1]), "=r"(r[2]), "=r"(r[3]) : "r"(addr));
}
__device__ __forceinline__ void ldm_x4_t(u32 addr, u32 r[4]) {
    asm volatile("ldmatrix.sync.aligned.m8n8.x4.trans.shared.b16 {%0,%1,%2,%3}, [%4];"
        : "=r"(r[0]), "=r"(r[1]), "=r"(r[2]), "=r"(r[3]) : "r"(addr));
}
__device__ __forceinline__ void mma_f16(float c[4], const u32 a[4], u32 b0, u32 b1) {
    asm volatile("mma.sync.aligned.m16n8k16.row.col.f32.f16.f16.f32 "
        "{%0,%1,%2,%3}, {%4,%5,%6,%7}, {%8,%9}, {%0,%1,%2,%3};"
        : "+f"(c[0]), "+f"(c[1]), "+f"(c[2]), "+f"(c[3])
        : "r"(a[0]), "r"(a[1]), "r"(a[2]), "r"(a[3]), "r"(b0), "r"(b1));
}

// XOR swizzles (c = 16B chunk index within row)
__device__ __forceinline__ u32 sw_a(u32 base, int row, int c) {       // 64B rows
    return base + row * 64 + ((c ^ ((row >> 1) & 3)) << 4);
}
__device__ __forceinline__ u32 sw_b(u32 base, int row, int c) {       // 256B rows
    return base + row * 256 + ((c ^ (row & 7)) << 4);
}
__device__ __forceinline__ u32 sw_b512(u32 base, int row, int c) {    // 512B rows
    return base + row * 512 + ((c ^ (row & 7)) << 4);
}

#define ZERO_ACC(acc)                                                         \
    _Pragma("unroll") for (int mi = 0; mi < 2; ++mi)                          \
    _Pragma("unroll") for (int ni = 0; ni < 8; ++ni)                          \
    _Pragma("unroll") for (int q = 0; q < 4; ++q) acc[mi][ni][q] = 0.0f;

// ---------------------------------------------------------------------------
// K1 building blocks (256 threads, B rows 256B, CTA 128x128)
// ---------------------------------------------------------------------------
__device__ __forceinline__ void stage_s(u32 base, int tid,
    const __half* __restrict__ a, size_t apitch,
    const __half* __restrict__ b, size_t bpitch, int k0)
{
    const int arow = tid >> 1, ac = tid & 1;
    const int brow = tid >> 3, bc = tid & 7;
    const __half* g = a + (size_t)arow * apitch + k0 + ac * 16;
    cpa16(sw_a(base, arow, ac * 2), g);
    cpa16(sw_a(base, arow, ac * 2 + 1), g + 8);
    g = b + (size_t)(k0 + brow) * bpitch + bc * 16;
    cpa16(sw_b(base + 8192, brow, bc * 2), g);
    cpa16(sw_b(base + 8192, brow, bc * 2 + 1), g + 8);
}
__device__ __forceinline__ void compute_s(float acc[2][8][4],
        u32 base, int warpM, int warpN, int lane)
{
    const int lr = lane & 15, lh = lane >> 4;
#pragma unroll
    for (int kk = 0; kk < 2; ++kk) {
        u32 af[2][4];
#pragma unroll
        for (int mi = 0; mi < 2; ++mi)
            ldm_x4(sw_a(base, warpM * 32 + mi * 16 + lr, kk * 2 + lh), af[mi]);
#pragma unroll
        for (int np = 0; np < 4; ++np) {
            u32 bf[4];
            ldm_x4_t(sw_b(base + 8192, kk * 16 + lr, warpN * 8 + np * 2 + lh), bf);
#pragma unroll
            for (int mi = 0; mi < 2; ++mi) {
                mma_f16(acc[mi][np*2],   af[mi], bf[0], bf[1]);
                mma_f16(acc[mi][np*2+1], af[mi], bf[2], bf[3]);
            }
        }
    }
}

// ---------------------------------------------------------------------------
// K23 building blocks (512 threads, B rows 512B, CTA 128x256)
// ---------------------------------------------------------------------------
__device__ __forceinline__ void stage_f(u32 base, int tid,
    const __half* __restrict__ a, const __half* __restrict__ b, int k0)
{
    const int arow = tid >> 2, ac = tid & 3;
    cpa16(sw_a(base, arow, ac), a + (size_t)arow * 256 + k0 + ac * 8);
    const int brow = tid >> 4, bc = (tid & 15) * 2;
    const __half* g = b + (size_t)(k0 + brow) * 256 + bc * 8;
    cpa16(sw_b512(base + 8192, brow, bc), g);
    cpa16(sw_b512(base + 8192, brow, bc + 1), g + 8);
}
__device__ __forceinline__ void stage_fB(u32 base, int tid,
    const __half* __restrict__ b, int k0)
{
    const int brow = tid >> 4, bc = (tid & 15) * 2;
    const __half* g = b + (size_t)(k0 + brow) * 256 + bc * 8;
    cpa16(sw_b512(base, brow, bc), g);
    cpa16(sw_b512(base, brow, bc + 1), g + 8);
}
// single-A (l2 staged) GEMM chunk
__device__ __forceinline__ void compute_f(float acc[2][8][4],
        u32 base, int warpM, int warpN, int lane)
{
    const int lr = lane & 15, lh = lane >> 4;
#pragma unroll
    for (int kk = 0; kk < 2; ++kk) {
        u32 af[2][4];
#pragma unroll
        for (int mi = 0; mi < 2; ++mi)
            ldm_x4(sw_a(base, warpM * 32 + mi * 16 + lr, kk * 2 + lh), af[mi]);
#pragma unroll
        for (int np = 0; np < 4; ++np) {
            u32 bf[4];
            ldm_x4_t(sw_b512(base + 8192, kk * 16 + lr, warpN * 8 + np * 2 + lh), bf);
#pragma unroll
            for (int mi = 0; mi < 2; ++mi) {
                mma_f16(acc[mi][np*2],   af[mi], bf[0], bf[1]);
                mma_f16(acc[mi][np*2+1], af[mi], bf[2], bf[3]);
            }
        }
    }
}
// pair-A (P resident in smem) GEMM chunk; sChunk = s*4 global k-chunk base
__device__ __forceinline__ void compute_fp(float acc[2][8][4],
        u32 pHi, u32 pLo, u32 bBase, int sChunk, int warpM, int warpN, int lane)
{
    const int lr = lane & 15, lh = lane >> 4;
#pragma unroll
    for (int kk = 0; kk < 2; ++kk) {
        u32 afh[2][4], afl[2][4];
#pragma unroll
        for (int mi = 0; mi < 2; ++mi) {
            int row = warpM * 32 + mi * 16 + lr;
            int c = sChunk + kk * 2 + lh;
            u32 off = row * 512 + (((c ^ (row & 7))) << 4);
            ldm_x4(pHi + off, afh[mi]);
            ldm_x4(pLo + off, afl[mi]);
        }
#pragma unroll
        for (int np = 0; np < 4; ++np) {
            u32 bf[4];
            ldm_x4_t(sw_b512(bBase, kk * 16 + lr, warpN * 8 + np * 2 + lh), bf);
#pragma unroll
            for (int mi = 0; mi < 2; ++mi) {
                mma_f16(acc[mi][np*2],   afh[mi], bf[0], bf[1]);
                mma_f16(acc[mi][np*2],   afl[mi], bf[0], bf[1]);
                mma_f16(acc[mi][np*2+1], afh[mi], bf[2], bf[3]);
                mma_f16(acc[mi][np*2+1], afl[mi], bf[2], bf[3]);
            }
        }
    }
}

// 3-buffer pipeline, prefetch depth 2, one barrier per BK=32 stage
#define FLOOP(STG, CMP)                                                       \
    STG(0, 0); CPA_COMMIT();                                                  \
    STG(1, 1); CPA_COMMIT();                                                  \
    for (int s = 0; s < 8; ++s) {                                             \
        if (s == 7) { CPA_WAIT(0); } else { CPA_WAIT(1); }                    \
        __syncthreads();                                                      \
        if (s < 6) { STG((s + 2) % 3, s + 2); CPA_COMMIT(); }                 \
        CMP;                                                                  \
    }

// K1 pipeline: 4 buffers, depth 3
#define MAINLOOP12(STG)                                                       \
    STG(0, 0); CPA_COMMIT();                                                  \
    STG(1, 1); CPA_COMMIT();                                                  \
    STG(2, 2); CPA_COMMIT();                                                  \
    for (int s = 0; s < 8; ++s) {                                             \
        if (s <= 5) { CPA_WAIT(2); } else if (s == 6) { CPA_WAIT(1); }        \
        else { CPA_WAIT(0); }                                                 \
        __syncthreads();                                                      \
        if (s < 5) { STG((s + 3) & 3, s + 3); CPA_COMMIT(); }                 \
        compute_s(acc, sb + (s & 3) * BUF12, warpM, warpN, lane);             \
    }

// ---------------------------------------------------------------------------
// Prep: fp32 -> fp16 (dest: 0 L1, 1 L2, 2 W1, 3 W2)
// ---------------------------------------------------------------------------
__global__ void k_prep(const float* __restrict__ src, int dest, size_t cnt)
{
    size_t i = ((size_t)blockIdx.x * 256 + threadIdx.x) * 8;
    if (i >= cnt) return;
    __half* d;
    switch (dest) {
        case 0:  d = g_L1; break;
        case 1:  d = g_L2; break;
        case 2:  d = g_W;  break;
        default: d = g_W + WSZ; break;
    }
    float4 v0 = *reinterpret_cast<const float4*>(src + i);
    float4 v1 = *reinterpret_cast<const float4*>(src + i + 4);
    float x[8] = {v0.x, v0.y, v0.z, v0.w, v1.x, v1.y, v1.z, v1.w};
    u32 o[4];
#pragma unroll
    for (int j = 0; j < 4; ++j) {
        __half2 h = __floats2half2_rn(x[2*j], x[2*j+1]);
        o[j] = *reinterpret_cast<u32*>(&h);
    }
    *reinterpret_cast<uint4*>(d + i) = make_uint4(o[0], o[1], o[2], o[3]);
}

__global__ void k_prep_w3(const float* __restrict__ W3)
{
    __shared__ float t[32][33];
    int bx = blockIdx.x * 32, by = blockIdx.y * 32;
    t[threadIdx.y][threadIdx.x] = W3[(size_t)(by + threadIdx.y) * 256 + bx + threadIdx.x];
    __syncthreads();
    g_W3T[(size_t)(bx + threadIdx.y) * 256 + by + threadIdx.x] =
        __float2half_rn(t[threadIdx.x][threadIdx.y]);
}

// ---------------------------------------------------------------------------
// K1: grid (16 mt, 514 nt, 2 w). D[128 m][128 bc], K=256 over a -> X fp16.
// ---------------------------------------------------------------------------
__global__ void __launch_bounds__(256, 2)
k1_gemm()
{
    extern __shared__ char smem[];
    const int tid = threadIdx.x, lane = tid & 31, wid = tid >> 5;
    const int warpM = wid & 3, warpN = wid >> 2;
    const int mBase = blockIdx.x * 128;
    const size_t n0 = (size_t)blockIdx.y * 128;
    const int w = blockIdx.z;
    const __half* WP = g_W + (size_t)w * WSZ + n0;
    __half* XP       = g_X + (size_t)w * XSZ;
    const __half* AP = g_L1 + (size_t)mBase * 256;
    const u32 sb = smem_u32(smem);

    float acc[2][8][4];
    ZERO_ACC(acc)

#define K1_STAGE(buf, s) stage_s(sb + (buf) * BUF12, tid, AP, 256, WP, 65792, (s) * 32)
    MAINLOOP12(K1_STAGE)
#undef K1_STAGE

    const int gq = lane >> 2, t = lane & 3;
#pragma unroll
    for (int mi = 0; mi < 2; ++mi) {
        int row = mBase + warpM * 32 + mi * 16 + gq;
#pragma unroll
        for (int ni = 0; ni < 8; ++ni) {
            int colL = warpN * 64 + ni * 8 + t * 2;
            __half2 b2 = *reinterpret_cast<const __half2*>(WP + 256ull * 65792 + colL);
            float b0 = __half2float(__low2half(b2));
            float b1 = __half2float(__high2half(b2));
            size_t col = n0 + colL;
            __half2 o0 = __floats2half2_rn(acc[mi][ni][0] + b0, acc[mi][ni][1] + b1);
            __half2 o1 = __floats2half2_rn(acc[mi][ni][2] + b0, acc[mi][ni][3] + b1);
            *reinterpret_cast<__half2*>(XP + (size_t)row * 65792 + col) = o0;
            *reinterpret_cast<__half2*>(XP + (size_t)(row + 8) * 65792 + col) = o1;
        }
    }
}

// ---------------------------------------------------------------------------
// K23 fused: grid (2 jt, 2048 m), 512 threads, CTA tile 128 j x 256 (c|d).
// ---------------------------------------------------------------------------
__global__ void __launch_bounds__(512, 1)
k23_fused(const float* __restrict__ h1, const float* __restrict__ h2,
          float* __restrict__ out)
{
    extern __shared__ char smem[];
    const int tid = threadIdx.x, lane = tid & 31, wid = tid >> 5;
    const int warpM = wid & 3, warpN = wid >> 2;     // 4 x 4 warps
    const int jt = blockIdx.x, m = blockIdx.y;
    const u32 sb = smem_u32(smem);
    const u32 pHi = sb + FSM_P, pLo = sb + FSM_P + 65536;
    float* Tp  = reinterpret_cast<float*>(smem + FSM_P);     // pitch 260 floats
    float* h1s = reinterpret_cast<float*>(smem + FSM_H);
    float* h2s = reinterpret_cast<float*>(smem + FSM_H + 1024);
    float* red = reinterpret_cast<float*>(smem + FSM_RED);

    const __half* AP  = g_L2 + ((size_t)(m >> 8) * 256 + (size_t)jt * 128) * 256;
    const __half* X1P = g_X + (size_t)m * 65792;
    const __half* X2P = g_X + XSZ + (size_t)m * 65792;

    if (tid < 256) {
        h1s[tid] = h1[(size_t)m * 256 + tid];
        h2s[tid] = h2[(size_t)m * 256 + tid];
    }

    const int gq = lane >> 2, t = lane & 3;
    float acc[2][8][4];

    // ---------------- stage 1: A_r = l2 @ X2 + bias, *h2 -> P pair ----------
    ZERO_ACC(acc)
#define S1(buf, s) stage_f(sb + (buf) * FBUF, tid, AP, X2P, (s) * 32)
    FLOOP(S1, compute_f(acc, sb + (s % 3) * FBUF, warpM, warpN, lane))
#undef S1

#pragma unroll
    for (int mi = 0; mi < 2; ++mi) {
        int j0 = warpM * 32 + mi * 16 + gq;
#pragma unroll
        for (int ni = 0; ni < 8; ++ni) {
            int c = warpN * 64 + ni * 8 + t * 2;
            __half2 b2 = *reinterpret_cast<const __half2*>(X2P + 65536 + c);
            float b0 = __half2float(__low2half(b2));
            float b1 = __half2float(__high2half(b2));
            float v00 = (acc[mi][ni][0] + b0) * h2s[c];
            float v01 = (acc[mi][ni][1] + b1) * h2s[c + 1];
            float v10 = (acc[mi][ni][2] + b0) * h2s[c];
            float v11 = (acc[mi][ni][3] + b1) * h2s[c + 1];
            u32 chunk = (u32)(warpN * 8 + ni);
            u32 o0 = j0 * 512 + ((chunk ^ (j0 & 7)) << 4) + t * 4;
            int j1 = j0 + 8;
            u32 o1 = j1 * 512 + ((chunk ^ (j1 & 7)) << 4) + t * 4;
            __half h0 = __float2half_rn(v00), hh1 = __float2half_rn(v01);
            __half l0 = __float2half_rn(v00 - __half2float(h0));
            __half l1 = __float2half_rn(v01 - __half2float(hh1));
            *reinterpret_cast<__half2*>(smem + (pHi - sb) + o0) = __halves2half2(h0, hh1);
            *reinterpret_cast<__half2*>(smem + (pLo - sb) + o0) = __halves2half2(l0, l1);
            h0 = __float2half_rn(v10); hh1 = __float2half_rn(v11);
            l0 = __float2half_rn(v10 - __half2float(h0));
            l1 = __float2half_rn(v11 - __half2float(hh1));
            *reinterpret_cast<__half2*>(smem + (pHi - sb) + o1) = __halves2half2(h0, hh1);
            *reinterpret_cast<__half2*>(smem + (pLo - sb) + o1) = __halves2half2(l0, l1);
        }
    }
    __syncthreads();   // P complete before stage-2 staging/compute

    // ---------------- stage 2: T = P(pair) @ W3T, *h1 -> T (overwrites P) ---
    ZERO_ACC(acc)
#define S2(buf, s) stage_fB(sb + (buf) * FBUF, tid, g_W3T, (s) * 32)
    FLOOP(S2, compute_fp(acc, pHi, pLo, sb + (s % 3) * FBUF, s * 4, warpM, warpN, lane))
#undef S2

    __syncthreads();   // all P reads done; safe to overwrite with T
#pragma unroll
    for (int mi = 0; mi < 2; ++mi) {
        int j0 = warpM * 32 + mi * 16 + gq;
#pragma unroll
        for (int ni = 0; ni < 8; ++ni) {
            int c = warpN * 64 + ni * 8 + t * 2;
            float s0 = h1s[c], s1 = h1s[c + 1];
            *reinterpret_cast<float2*>(Tp + (size_t)j0 * 260 + c) =
                make_float2(acc[mi][ni][0] * s0, acc[mi][ni][1] * s1);
            *reinterpret_cast<float2*>(Tp + (size_t)(j0 + 8) * 260 + c) =
                make_float2(acc[mi][ni][2] * s0, acc[mi][ni][3] * s1);
        }
    }
    __syncthreads();   // T visible before stage-3 epilogue; bufs free

    // ---------------- stage 3: A_l = l2 @ X1 + bias; dot with T -------------
    ZERO_ACC(acc)
#define S3(buf, s) stage_f(sb + (buf) * FBUF, tid, AP, X1P, (s) * 32)
    FLOOP(S3, compute_f(acc, sb + (s % 3) * FBUF, warpM, warpN, lane))
#undef S3

    float rs[2][2] = {{0.0f, 0.0f}, {0.0f, 0.0f}};
#pragma unroll
    for (int mi = 0; mi < 2; ++mi) {
        int j0 = warpM * 32 + mi * 16 + gq;
#pragma unroll
        for (int ni = 0; ni < 8; ++ni) {
            int c = warpN * 64 + ni * 8 + t * 2;
            __half2 b2 = *reinterpret_cast<const __half2*>(X1P + 65536 + c);
            float b0 = __half2float(__low2half(b2));
            float b1 = __half2float(__high2half(b2));
            float2 t0 = *reinterpret_cast<const float2*>(Tp + (size_t)j0 * 260 + c);
            float2 t1 = *reinterpret_cast<const float2*>(Tp + (size_t)(j0 + 8) * 260 + c);
            rs[mi][0] += (acc[mi][ni][0] + b0) * t0.x + (acc[mi][ni][1] + b1) * t0.y;
            rs[mi][1] += (acc[mi][ni][2] + b0) * t1.x + (acc[mi][ni][3] + b1) * t1.y;
        }
    }

    // reduce over the 4 lanes (t) sharing each row, then across warpN
#pragma unroll
    for (int mi = 0; mi < 2; ++mi)
#pragma unroll
        for (int h = 0; h < 2; ++h) {
            rs[mi][h] += __shfl_xor_sync(0xffffffffu, rs[mi][h], 1);
            rs[mi][h] += __shfl_xor_sync(0xffffffffu, rs[mi][h], 2);
        }
    if (t == 0) {
#pragma unroll
        for (int mi = 0; mi < 2; ++mi) {
            red[warpN * 128 + warpM * 32 + mi * 16 + gq]     = rs[mi][0];
            red[warpN * 128 + warpM * 32 + mi * 16 + 8 + gq] = rs[mi][1];
        }
    }
    __syncthreads();
    if (tid < 128)
        out[(size_t)m * 256 + jt * 128 + tid] =
            red[tid] + red[128 + tid] + red[256 + tid] + red[384 + tid];
}

// ---------------------------------------------------------------------------
extern "C" void kernel_launch(void* const* d_in, const int* in_sizes, int n_in,
                              void* d_out, int out_size)
{
    const float* layer1 = (const float*)d_in[0];
    const float* layer2 = (const float*)d_in[1];
    const float* h1     = (const float*)d_in[2];
    const float* h2     = (const float*)d_in[3];
    const float* W1     = (const float*)d_in[4];
    const float* W2     = (const float*)d_in[5];
    const float* W3     = (const float*)d_in[6];
    float* out = (float*)d_out;

    cudaFuncSetAttribute(k1_gemm,   cudaFuncAttributeMaxDynamicSharedMemorySize, SMEM12);
    cudaFuncSetAttribute(k23_fused, cudaFuncAttributeMaxDynamicSharedMemorySize, FSMEM);

    k_prep<<<256,  256>>>(layer1, 0, 524288ull);
    k_prep<<<256,  256>>>(layer2, 1, 524288ull);
    k_prep<<<8257, 256>>>(W1, 2, WSZ);
    k_prep<<<8257, 256>>>(W2, 3, WSZ);
    k_prep_w3<<<dim3(8, 8), dim3(32, 32)>>>(W3);

    k1_gemm<<<dim3(16, 514, 2), 256, SMEM12>>>();
    k23_fused<<<dim3(2, 2048), 512, FSMEM>>>(h1, h2, out);
}